// round 1
// baseline (speedup 1.0000x reference)
#include <cuda_runtime.h>
#include <math.h>

// ---------------------------------------------------------------------------
// Problem constants
// ---------------------------------------------------------------------------
namespace {
constexpr int Bb   = 2;
constexpr int Ll   = 512;
constexpr int Vv   = 50304;
constexpr int Dd   = 768;
constexpr int NL   = 2;
constexpr int DI   = 1536;
constexpr int Ns   = 16;     // SSM state dim
constexpr int DTR  = 48;
constexpr int Hh   = 1536;
constexpr int CND  = 128;
constexpr int FREQ = 256;
constexpr int MASKID = 50257;
constexpr int BL   = Bb * Ll;                 // 1024
constexpr int DTBC = DTR + 2 * Ns;            // 80

constexpr size_t S_H    = (size_t)BL * Dd;        // 786432
constexpr size_t S_XZ   = (size_t)BL * 2 * DI;    // 3145728
constexpr size_t S_DTBC = (size_t)BL * DTBC;      // 81920
constexpr size_t S_DEL  = (size_t)BL * DI;        // 1572864
constexpr size_t S_YO   = (size_t)BL * Dd;
constexpr size_t S_MLP  = (size_t)BL * Hh;

constexpr size_t OFF_H     = 0;
constexpr size_t OFF_NORM  = OFF_H    + S_H;
constexpr size_t OFF_C     = OFF_NORM + S_H;
constexpr size_t OFF_COND  = OFF_C    + (size_t)Bb * CND;
constexpr size_t OFF_XZ    = OFF_COND + (size_t)Bb * 3 * Dd;
constexpr size_t OFF_DTBC  = OFF_XZ   + 2 * S_XZ;
constexpr size_t OFF_DELTA = OFF_DTBC + 2 * S_DTBC;
constexpr size_t OFF_Y     = OFF_DELTA + 2 * S_DEL;
constexpr size_t OFF_YO    = OFF_Y    + 2 * S_DEL;
constexpr size_t OFF_MLPA  = OFF_YO   + 2 * S_YO;
constexpr size_t OFF_MLPB  = OFF_MLPA + S_MLP;
constexpr size_t TOTALF    = OFF_MLPB + S_MLP;

constexpr float NEGF = -3.402823466e38f;   // finfo(float32).min
} // namespace

__device__ float g_buf[TOTALF];
__device__ int   g_midx[BL];
__device__ int   g_mcount;

__device__ __forceinline__ float siluf(float x) { return x / (1.f + __expf(-x)); }

// ---------------------------------------------------------------------------
// Embedding: h[b,l,:] = tok_emb[x_t[b,l]] + pos_emb[l]
// ---------------------------------------------------------------------------
__global__ void embed_k(const int* __restrict__ x_t, const float* __restrict__ tok,
                        const float* __restrict__ pos, float* __restrict__ h) {
  int row = blockIdx.x;
  int t   = x_t[row];
  int l   = row % Ll;
  const float* te = tok + (size_t)t * Dd;
  const float* pe = pos + (size_t)l * Dd;
  float* ho = h + (size_t)row * Dd;
  for (int d = threadIdx.x; d < Dd; d += blockDim.x) ho[d] = te[d] + pe[d];
}

// ---------------------------------------------------------------------------
// Sigma embedding + conditioning MLP: c = silu(emb@w1+b1)@w2+b2
// grid = B, block = 128
// ---------------------------------------------------------------------------
__global__ void sigma_cond_k(const float* __restrict__ sigma,
                             const float* __restrict__ w1, const float* __restrict__ b1,
                             const float* __restrict__ w2, const float* __restrict__ b2,
                             float* __restrict__ c) {
  __shared__ float emb[FREQ];
  __shared__ float hid[CND];
  int b = blockIdx.x, i = threadIdx.x;   // i in [0,128)
  float sg  = sigma[b];
  float f   = expf(-logf(10000.f) * (float)i / (float)(FREQ / 2));
  float arg = sg * f;
  emb[i]            = cosf(arg);
  emb[i + FREQ / 2] = sinf(arg);
  __syncthreads();
  float acc = b1[i];
  for (int j = 0; j < FREQ; j++) acc += emb[j] * w1[j * CND + i];
  hid[i] = siluf(acc);
  __syncthreads();
  float acc2 = b2[i];
  for (int j = 0; j < CND; j++) acc2 += hid[j] * w2[j * CND + i];
  c[b * CND + i] = acc2;
}

// ---------------------------------------------------------------------------
// adaLN conditioning vector: cond[b, 0:3D] = c[b] @ W + bias
// ---------------------------------------------------------------------------
__global__ void adaln_cond_k(const float* __restrict__ c, const float* __restrict__ W,
                             const float* __restrict__ bias, float* __restrict__ cond) {
  int o = blockIdx.x * blockDim.x + threadIdx.x;
  if (o >= Bb * 3 * Dd) return;
  int b = o / (3 * Dd), col = o % (3 * Dd);
  float acc = bias[col];
  const float* cb = c + b * CND;
  for (int j = 0; j < CND; j++) acc += cb[j] * W[(size_t)j * 3 * Dd + col];
  cond[o] = acc;
}

// ---------------------------------------------------------------------------
// LayerNorm + adaLN modulate: out = LN(h)*(1+scale)+shift
// grid = BL, block = 256 (D = 768 = 3*256)
// ---------------------------------------------------------------------------
__global__ void ln_mod_k(const float* __restrict__ h, const float* __restrict__ cond,
                         float* __restrict__ out) {
  __shared__ float red[256];
  int row = blockIdx.x, tid = threadIdx.x;
  int b = row / Ll;
  const float* x = h + (size_t)row * Dd;
  float v0 = x[tid], v1 = x[tid + 256], v2 = x[tid + 512];
  red[tid] = v0 + v1 + v2;
  __syncthreads();
  for (int s = 128; s > 0; s >>= 1) { if (tid < s) red[tid] += red[tid + s]; __syncthreads(); }
  float mu = red[0] / (float)Dd;
  __syncthreads();
  float d0 = v0 - mu, d1 = v1 - mu, d2 = v2 - mu;
  red[tid] = d0 * d0 + d1 * d1 + d2 * d2;
  __syncthreads();
  for (int s = 128; s > 0; s >>= 1) { if (tid < s) red[tid] += red[tid + s]; __syncthreads(); }
  float r = rsqrtf(red[0] / (float)Dd + 1e-5f);
  const float* shift = cond + (size_t)b * 3 * Dd;
  const float* scale = shift + Dd;
  float* o = out + (size_t)row * Dd;
  o[tid]       = d0 * r * (1.f + scale[tid])       + shift[tid];
  o[tid + 256] = d1 * r * (1.f + scale[tid + 256]) + shift[tid + 256];
  o[tid + 512] = d2 * r * (1.f + scale[tid + 512]) + shift[tid + 512];
}

// ---------------------------------------------------------------------------
// Generic fp32 GEMM: C[M,N] = A[M,K] @ B[K,N], row-major, strided.
// 64x64 block tile, BK=16, 256 threads, 4x4 per-thread microtile.
// ---------------------------------------------------------------------------
__global__ void gemm_k(const float* __restrict__ A, const float* __restrict__ B,
                       float* __restrict__ C, int M, int Nn, int K,
                       int lda, int ldb, int ldc) {
  __shared__ float As[16][64];
  __shared__ float Bs[16][64];
  int tid = threadIdx.x;
  int m0 = blockIdx.y * 64;
  int n0 = blockIdx.x * 64;
  int tx = tid & 15, ty = tid >> 4;
  float acc[4][4] = {};
  for (int k0 = 0; k0 < K; k0 += 16) {
    {
      int r = tid >> 2, cb = (tid & 3) * 4;
      int gm = m0 + r;
#pragma unroll
      for (int i = 0; i < 4; i++) {
        int gk = k0 + cb + i;
        As[cb + i][r] = (gm < M && gk < K) ? A[(size_t)gm * lda + gk] : 0.f;
      }
    }
    {
      int r = tid >> 4, cb = (tid & 15) * 4;
      int gk = k0 + r;
#pragma unroll
      for (int i = 0; i < 4; i++) {
        int gn = n0 + cb + i;
        Bs[r][cb + i] = (gk < K && gn < Nn) ? B[(size_t)gk * ldb + gn] : 0.f;
      }
    }
    __syncthreads();
#pragma unroll
    for (int kk = 0; kk < 16; kk++) {
      float4 av = *reinterpret_cast<const float4*>(&As[kk][ty * 4]);
      float4 bv = *reinterpret_cast<const float4*>(&Bs[kk][tx * 4]);
      float a_[4] = {av.x, av.y, av.z, av.w};
      float b_[4] = {bv.x, bv.y, bv.z, bv.w};
#pragma unroll
      for (int i = 0; i < 4; i++)
#pragma unroll
        for (int j = 0; j < 4; j++) acc[i][j] = fmaf(a_[i], b_[j], acc[i][j]);
    }
    __syncthreads();
  }
#pragma unroll
  for (int i = 0; i < 4; i++) {
    int gm = m0 + ty * 4 + i;
    if (gm >= M) continue;
#pragma unroll
    for (int j = 0; j < 4; j++) {
      int gn = n0 + tx * 4 + j;
      if (gn < Nn) C[(size_t)gm * ldc + gn] = acc[i][j];
    }
  }
}

// ---------------------------------------------------------------------------
// delta = softplus(delta + dt_bias[d])
// ---------------------------------------------------------------------------
__global__ void softplus_bias_k(float* __restrict__ delta, const float* __restrict__ dtb) {
  int i = blockIdx.x * blockDim.x + threadIdx.x;
  if (i >= BL * DI) return;
  float x = delta[i] + dtb[i % DI];
  delta[i] = fmaxf(x, 0.f) + log1pf(__expf(-fabsf(x)));
}

// ---------------------------------------------------------------------------
// Selective-scan. One thread per (d, n). 16-lane shuffle reduce over n.
// grid = (DI/16, B), block = 256 (16 d-channels x 16 n-lanes)
// ---------------------------------------------------------------------------
__global__ void scan_k(const float* __restrict__ delta, const float* __restrict__ xz,
                       const float* __restrict__ dtbc, const float* __restrict__ A_log,
                       float* __restrict__ y, int backward) {
  int tid = threadIdx.x;
  int nloc = tid & 15, dloc = tid >> 4;
  int d = blockIdx.x * 16 + dloc;
  int b = blockIdx.y;
  float a = -expf(A_log[d * Ns + nloc]);
  float hst = 0.f;
  for (int s = 0; s < Ll; s++) {
    int t = backward ? (Ll - 1 - s) : s;
    size_t row = (size_t)b * Ll + t;
    float dl = delta[row * DI + d];
    float u  = xz[row * 2 * DI + d];
    float Bv = dtbc[row * DTBC + DTR + nloc];
    float Cv = dtbc[row * DTBC + DTR + Ns + nloc];
    hst = __expf(dl * a) * hst + dl * u * Bv;
    float ctr = hst * Cv;
    ctr += __shfl_down_sync(0xffffffffu, ctr, 8, 16);
    ctr += __shfl_down_sync(0xffffffffu, ctr, 4, 16);
    ctr += __shfl_down_sync(0xffffffffu, ctr, 2, 16);
    ctr += __shfl_down_sync(0xffffffffu, ctr, 1, 16);
    if (nloc == 0) y[row * DI + d] = ctr;
  }
}

// ---------------------------------------------------------------------------
// y = (y + u*Dskip) * silu(z)   (in place)
// ---------------------------------------------------------------------------
__global__ void gate_k(float* __restrict__ y, const float* __restrict__ xz,
                       const float* __restrict__ Dsk) {
  int i = blockIdx.x * blockDim.x + threadIdx.x;
  if (i >= BL * DI) return;
  int d = i % DI;
  size_t row = (size_t)(i / DI);
  float u = xz[row * 2 * DI + d];
  float z = xz[row * 2 * DI + DI + d];
  y[i] = (y[i] + u * Dsk[d]) * siluf(z);
}

// ---------------------------------------------------------------------------
// h += gate * (p0 [+ p1])
// ---------------------------------------------------------------------------
__global__ void combine_k(float* __restrict__ h, const float* __restrict__ cond,
                          const float* __restrict__ p0, const float* __restrict__ p1) {
  int i = blockIdx.x * blockDim.x + threadIdx.x;
  if (i >= BL * Dd) return;
  int d = i % Dd;
  int b = i / (Ll * Dd);
  float g = cond[(size_t)b * 3 * Dd + 2 * Dd + d];
  float v = p0[i];
  if (p1) v += p1[i];
  h[i] += g * v;
}

// a = silu(a) * bm
__global__ void silu_mul_k(float* __restrict__ a, const float* __restrict__ bm) {
  int i = blockIdx.x * blockDim.x + threadIdx.x;
  if (i >= BL * Hh) return;
  a[i] = siluf(a[i]) * bm[i];
}

// ---------------------------------------------------------------------------
// Compact list of masked rows (x_t == MASK_ID). Single block of 1024.
// ---------------------------------------------------------------------------
__global__ void build_mask_k(const int* __restrict__ x_t, int* __restrict__ midx,
                             int* __restrict__ mcount) {
  __shared__ int sf[BL];
  int i = threadIdx.x;
  int f = (x_t[i] == MASKID) ? 1 : 0;
  sf[i] = f;
  __syncthreads();
  for (int off = 1; off < BL; off <<= 1) {
    int v = (i >= off) ? sf[i - off] : 0;
    __syncthreads();
    sf[i] += v;
    __syncthreads();
  }
  if (f) midx[sf[i] - 1] = i;
  if (i == BL - 1) *mcount = sf[i];
}

// ---------------------------------------------------------------------------
// Unmasked rows: forced pattern (0 at token, NEG elsewhere)
// ---------------------------------------------------------------------------
__global__ void fill_forced_k(const int* __restrict__ x_t, float* __restrict__ out) {
  int row = blockIdx.x;
  int tok = x_t[row];
  if (tok == MASKID) return;
  float4* o = reinterpret_cast<float4*>(out + (size_t)row * Vv);
  for (int v4 = threadIdx.x; v4 < Vv / 4; v4 += blockDim.x) {
    int v = v4 * 4;
    float4 val = make_float4(NEGF, NEGF, NEGF, NEGF);
    if (tok >= v && tok < v + 4) (&val.x)[tok - v] = 0.f;
    o[v4] = val;
  }
}

// ---------------------------------------------------------------------------
// Logits GEMM over masked rows only: out[r, v] = normed[r,:] . tok_emb[v,:]
// B is transposed-layout (V, D). Rows gathered through midx.
// ---------------------------------------------------------------------------
__global__ void gemm_logits_k(const float* __restrict__ A, const float* __restrict__ Bw,
                              float* __restrict__ out, const int* __restrict__ midx,
                              const int* __restrict__ mcount) {
  int M = *mcount;
  int m0 = blockIdx.y * 64;
  if (m0 >= M) return;
  __shared__ float As[16][64];
  __shared__ float Bs[16][64];
  __shared__ int rows[64];
  int tid = threadIdx.x;
  if (tid < 64) rows[tid] = (m0 + tid < M) ? midx[m0 + tid] : -1;
  __syncthreads();
  int n0 = blockIdx.x * 64;
  int tx = tid & 15, ty = tid >> 4;
  float acc[4][4] = {};
  for (int k0 = 0; k0 < Dd; k0 += 16) {
    {
      int r = tid >> 2, cb = (tid & 3) * 4;
      int gr = rows[r];
      float4 av = make_float4(0.f, 0.f, 0.f, 0.f);
      if (gr >= 0) av = *reinterpret_cast<const float4*>(A + (size_t)gr * Dd + k0 + cb);
      As[cb + 0][r] = av.x; As[cb + 1][r] = av.y;
      As[cb + 2][r] = av.z; As[cb + 3][r] = av.w;
    }
    {
      int r = tid >> 2, cb = (tid & 3) * 4;
      int gn = n0 + r;   // V multiple of 64, always valid
      float4 bv = *reinterpret_cast<const float4*>(Bw + (size_t)gn * Dd + k0 + cb);
      Bs[cb + 0][r] = bv.x; Bs[cb + 1][r] = bv.y;
      Bs[cb + 2][r] = bv.z; Bs[cb + 3][r] = bv.w;
    }
    __syncthreads();
#pragma unroll
    for (int kk = 0; kk < 16; kk++) {
      float4 av = *reinterpret_cast<const float4*>(&As[kk][ty * 4]);
      float4 bv = *reinterpret_cast<const float4*>(&Bs[kk][tx * 4]);
      float a_[4] = {av.x, av.y, av.z, av.w};
      float b_[4] = {bv.x, bv.y, bv.z, bv.w};
#pragma unroll
      for (int i = 0; i < 4; i++)
#pragma unroll
        for (int j = 0; j < 4; j++) acc[i][j] = fmaf(a_[i], b_[j], acc[i][j]);
    }
    __syncthreads();
  }
#pragma unroll
  for (int i = 0; i < 4; i++) {
    int gr = rows[ty * 4 + i];
    if (gr < 0) continue;
    float4* o = reinterpret_cast<float4*>(out + (size_t)gr * Vv + n0 + tx * 4);
    *o = make_float4(acc[i][0], acc[i][1], acc[i][2], acc[i][3]);
  }
}

// ---------------------------------------------------------------------------
// In-place log-softmax on masked rows; MASK_ID column forced to NEG.
// ---------------------------------------------------------------------------
__global__ void log_softmax_k(const int* __restrict__ x_t, float* __restrict__ out) {
  __shared__ float red[256];
  int row = blockIdx.x;
  if (x_t[row] != MASKID) return;
  float* o = out + (size_t)row * Vv;
  int tid = threadIdx.x;
  float m = NEGF;
  for (int v = tid; v < Vv; v += 256)
    if (v != MASKID) m = fmaxf(m, o[v]);
  red[tid] = m;
  __syncthreads();
  for (int s = 128; s > 0; s >>= 1) { if (tid < s) red[tid] = fmaxf(red[tid], red[tid + s]); __syncthreads(); }
  m = red[0];
  __syncthreads();
  float sum = 0.f;
  for (int v = tid; v < Vv; v += 256)
    if (v != MASKID) sum += __expf(o[v] - m);
  red[tid] = sum;
  __syncthreads();
  for (int s = 128; s > 0; s >>= 1) { if (tid < s) red[tid] += red[tid + s]; __syncthreads(); }
  float lse = m + logf(red[0]);
  __syncthreads();
  for (int v = tid; v < Vv; v += 256)
    o[v] = (v == MASKID) ? NEGF : (o[v] - lse);
}

// ---------------------------------------------------------------------------
// Host: launch sequence (graph-capturable, no allocs, no syncs)
// ---------------------------------------------------------------------------
static inline void run_gemm(const float* A, const float* B, float* C,
                            int M, int N, int K, int lda, int ldb, int ldc) {
  dim3 g((N + 63) / 64, (M + 63) / 64);
  gemm_k<<<g, 256>>>(A, B, C, M, N, K, lda, ldb, ldc);
}

extern "C" void kernel_launch(void* const* d_in, const int* in_sizes, int n_in,
                              void* d_out, int out_size) {
  (void)in_sizes; (void)n_in; (void)out_size;
  const int*   x_t      = (const int*)  d_in[0];
  const float* sigma    = (const float*)d_in[1];
  const float* tok_emb  = (const float*)d_in[2];
  const float* pos_emb  = (const float*)d_in[3];
  const float* te_w1    = (const float*)d_in[4];
  const float* te_b1    = (const float*)d_in[5];
  const float* te_w2    = (const float*)d_in[6];
  const float* te_b2    = (const float*)d_in[7];
  const float* adaln1_w = (const float*)d_in[8];
  const float* adaln1_b = (const float*)d_in[9];
  const float* adaln2_w = (const float*)d_in[10];
  const float* adaln2_b = (const float*)d_in[11];
  const float* Win      = (const float*)d_in[12];
  const float* Wx       = (const float*)d_in[13];
  const float* Wdt      = (const float*)d_in[14];
  const float* dt_bias  = (const float*)d_in[15];
  const float* A_log    = (const float*)d_in[16];
  const float* Dskip    = (const float*)d_in[17];
  const float* Wout     = (const float*)d_in[18];
  const float* mlp_w1   = (const float*)d_in[19];
  const float* mlp_w2   = (const float*)d_in[20];
  const float* mlp_w3   = (const float*)d_in[21];
  const float* oad_w    = (const float*)d_in[22];
  const float* oad_b    = (const float*)d_in[23];
  float* out = (float*)d_out;

  float* buf = nullptr;
  int* midx = nullptr;
  int* mcount = nullptr;
  cudaGetSymbolAddress((void**)&buf, g_buf);
  cudaGetSymbolAddress((void**)&midx, g_midx);
  cudaGetSymbolAddress((void**)&mcount, g_mcount);

  float* h     = buf + OFF_H;
  float* norm  = buf + OFF_NORM;
  float* c     = buf + OFF_C;
  float* cond  = buf + OFF_COND;
  float* xz[2]    = {buf + OFF_XZ,    buf + OFF_XZ    + S_XZ};
  float* dtbc[2]  = {buf + OFF_DTBC,  buf + OFF_DTBC  + S_DTBC};
  float* delta[2] = {buf + OFF_DELTA, buf + OFF_DELTA + S_DEL};
  float* yb[2]    = {buf + OFF_Y,     buf + OFF_Y     + S_DEL};
  float* yo[2]    = {buf + OFF_YO,    buf + OFF_YO    + S_YO};
  float* mlpa  = buf + OFF_MLPA;
  float* mlpb  = buf + OFF_MLPB;

  embed_k<<<BL, 256>>>(x_t, tok_emb, pos_emb, h);
  sigma_cond_k<<<Bb, 128>>>(sigma, te_w1, te_b1, te_w2, te_b2, c);
  build_mask_k<<<1, BL>>>(x_t, midx, mcount);
  fill_forced_k<<<BL, 256>>>(x_t, out);

  const int EW_DI = (BL * DI + 255) / 256;   // elementwise grid over BL*DI
  const int EW_D  = (BL * Dd + 255) / 256;
  const int EW_H  = (BL * Hh + 255) / 256;

  for (int l = 0; l < NL; l++) {
    // ---- SSM block ----
    adaln_cond_k<<<(Bb * 3 * Dd) / 256, 256>>>(c, adaln1_w + (size_t)l * CND * 3 * Dd,
                                               adaln1_b + (size_t)l * 3 * Dd, cond);
    ln_mod_k<<<BL, 256>>>(h, cond, norm);
    for (int dir = 0; dir < 2; dir++) {
      int li = l * 2 + dir;
      run_gemm(norm, Win + (size_t)li * Dd * 2 * DI, xz[dir],
               BL, 2 * DI, Dd, Dd, 2 * DI, 2 * DI);
      run_gemm(xz[dir], Wx + (size_t)li * DI * DTBC, dtbc[dir],
               BL, DTBC, DI, 2 * DI, DTBC, DTBC);
      run_gemm(dtbc[dir], Wdt + (size_t)li * DTR * DI, delta[dir],
               BL, DI, DTR, DTBC, DI, DI);
      softplus_bias_k<<<EW_DI, 256>>>(delta[dir], dt_bias + (size_t)li * DI);
    }
    for (int dir = 0; dir < 2; dir++) {
      int li = l * 2 + dir;
      scan_k<<<dim3(DI / 16, Bb), 256>>>(delta[dir], xz[dir], dtbc[dir],
                                         A_log + (size_t)li * DI * Ns, yb[dir], dir);
    }
    for (int dir = 0; dir < 2; dir++) {
      int li = l * 2 + dir;
      gate_k<<<EW_DI, 256>>>(yb[dir], xz[dir], Dskip + (size_t)li * DI);
      run_gemm(yb[dir], Wout + (size_t)li * DI * Dd, yo[dir],
               BL, Dd, DI, DI, Dd, Dd);
    }
    combine_k<<<EW_D, 256>>>(h, cond, yo[0], yo[1]);

    // ---- MLP block ----
    adaln_cond_k<<<(Bb * 3 * Dd) / 256, 256>>>(c, adaln2_w + (size_t)l * CND * 3 * Dd,
                                               adaln2_b + (size_t)l * 3 * Dd, cond);
    ln_mod_k<<<BL, 256>>>(h, cond, norm);
    run_gemm(norm, mlp_w1 + (size_t)l * Dd * Hh, mlpa, BL, Hh, Dd, Dd, Hh, Hh);
    run_gemm(norm, mlp_w2 + (size_t)l * Dd * Hh, mlpb, BL, Hh, Dd, Dd, Hh, Hh);
    silu_mul_k<<<EW_H, 256>>>(mlpa, mlpb);
    run_gemm(mlpa, mlp_w3 + (size_t)l * Hh * Dd, yo[0], BL, Dd, Hh, Hh, Dd, Dd);
    combine_k<<<EW_D, 256>>>(h, cond, yo[0], nullptr);
  }

  // ---- Output head ----
  adaln_cond_k<<<(Bb * 3 * Dd) / 256, 256>>>(c, oad_w, oad_b, cond);
  ln_mod_k<<<BL, 256>>>(h, cond, norm);
  gemm_logits_k<<<dim3(Vv / 64, BL / 64), 256>>>(norm, tok_emb, out, midx, mcount);
  log_softmax_k<<<BL, 256>>>(x_t, out);
}

// round 2
// speedup vs baseline: 2.4071x; 2.4071x over previous
#include <cuda_runtime.h>
#include <cuda_bf16.h>
#include <math.h>

// ---------------------------------------------------------------------------
// Problem constants
// ---------------------------------------------------------------------------
namespace {
constexpr int Bb   = 2;
constexpr int Ll   = 512;
constexpr int Vv   = 50304;
constexpr int Dd   = 768;
constexpr int NL   = 2;
constexpr int DI   = 1536;
constexpr int Ns   = 16;
constexpr int DTR  = 48;
constexpr int Hh   = 1536;
constexpr int CND  = 128;
constexpr int FREQ = 256;
constexpr int MASKID = 50257;
constexpr int BL   = Bb * Ll;                 // 1024
constexpr int DTBC = DTR + 2 * Ns;            // 80

// fp32 scratch pool offsets
constexpr size_t S_H    = (size_t)BL * Dd;
constexpr size_t S_XZ   = (size_t)BL * 2 * DI;
constexpr size_t S_DTBC = (size_t)BL * DTBC;
constexpr size_t S_DEL  = (size_t)BL * DI;
constexpr size_t S_YO   = (size_t)BL * Dd;
constexpr size_t S_MLP  = (size_t)BL * Hh;

constexpr size_t OFF_H     = 0;
constexpr size_t OFF_C     = OFF_H    + S_H;
constexpr size_t OFF_COND  = OFF_C    + (size_t)Bb * CND;
constexpr size_t OFF_XZ    = OFF_COND + (size_t)Bb * 3 * Dd;
constexpr size_t OFF_DTBC  = OFF_XZ   + 2 * S_XZ;
constexpr size_t OFF_DELTA = OFF_DTBC + 2 * S_DTBC;
constexpr size_t OFF_Y     = OFF_DELTA + 2 * S_DEL;
constexpr size_t OFF_YO    = OFF_Y    + 2 * S_DEL;
constexpr size_t OFF_MLPA  = OFF_YO   + 2 * S_YO;
constexpr size_t OFF_MLPB  = OFF_MLPA + S_MLP;
constexpr size_t TOTALF    = OFF_MLPB + S_MLP;

// bf16 pool offsets (element counts; all multiples of 8 -> 16B aligned)
constexpr size_t HS_TE    = (size_t)Vv * Dd;                  // 38,633,472
constexpr size_t HS_WINT  = (size_t)2 * DI * Dd;              // 2,359,296 each
constexpr size_t HS_WXT   = (size_t)DTBC * DI;                // 122,880 each
constexpr size_t HS_WDTT  = (size_t)DI * DTR;                 // 73,728 each
constexpr size_t HS_WOUTT = (size_t)Dd * DI;                  // 1,179,648 each
constexpr size_t HS_W12T  = (size_t)Hh * Dd;                  // 1,179,648 each
constexpr size_t HS_W3T   = (size_t)Dd * Hh;                  // 1,179,648 each

constexpr size_t HB_TE    = 0;
constexpr size_t HB_WINT  = HB_TE    + HS_TE;
constexpr size_t HB_WXT   = HB_WINT  + 4 * HS_WINT;
constexpr size_t HB_WDTT  = HB_WXT   + 4 * HS_WXT;
constexpr size_t HB_WOUTT = HB_WDTT  + 4 * HS_WDTT;
constexpr size_t HB_W12T  = HB_WOUTT + 4 * HS_WOUTT;          // l0w1,l0w2,l1w1,l1w2
constexpr size_t HB_W3T   = HB_W12T  + 4 * HS_W12T;
constexpr size_t HB_NORM  = HB_W3T   + 2 * HS_W3T;
constexpr size_t HB_XZ    = HB_NORM  + (size_t)BL * Dd;
constexpr size_t HB_DTBC  = HB_XZ    + 2 * (size_t)BL * 2 * DI;
constexpr size_t HB_Y     = HB_DTBC  + 2 * (size_t)BL * DTBC;
constexpr size_t HB_MLPA  = HB_Y     + 2 * (size_t)BL * DI;
constexpr size_t TOTALH   = HB_MLPA  + (size_t)BL * Hh + 64;

constexpr float NEGF = -3.402823466e38f;
} // namespace

__device__ float g_buf[TOTALF];
__device__ __align__(16) __nv_bfloat16 g_bf[TOTALH];
__device__ int   g_midx[BL];
__device__ int   g_mcount;

__device__ __forceinline__ float siluf(float x) { return x / (1.f + __expf(-x)); }

// ---------------------------------------------------------------------------
// Weight preprocessing: fp32 -> bf16, with optional transpose to [N][K].
// ---------------------------------------------------------------------------
__global__ void conv_k(const float* __restrict__ in, __nv_bfloat16* __restrict__ out, int n) {
  int i = (blockIdx.x * blockDim.x + threadIdx.x) * 4;
  if (i + 3 >= n) {
    for (; i < n; i++) out[i] = __float2bfloat16(in[i]);
    return;
  }
  float4 v = *reinterpret_cast<const float4*>(in + i);
  __nv_bfloat162 a = __floats2bfloat162_rn(v.x, v.y);
  __nv_bfloat162 b = __floats2bfloat162_rn(v.z, v.w);
  *reinterpret_cast<__nv_bfloat162*>(out + i)     = a;
  *reinterpret_cast<__nv_bfloat162*>(out + i + 2) = b;
}

// out[n][k] = bf16(in[k][n]);  in is [K][N] row-major
__global__ void tconv_k(const float* __restrict__ in, __nv_bfloat16* __restrict__ out,
                        int K, int N) {
  __shared__ float tile[32][33];
  int k0 = blockIdx.y * 32, n0 = blockIdx.x * 32;
  int x = threadIdx.x, y = threadIdx.y;   // 32 x 8
#pragma unroll
  for (int i = 0; i < 32; i += 8) {
    int k = k0 + y + i, n = n0 + x;
    tile[y + i][x] = (k < K && n < N) ? in[(size_t)k * N + n] : 0.f;
  }
  __syncthreads();
#pragma unroll
  for (int i = 0; i < 32; i += 8) {
    int n = n0 + y + i, k = k0 + x;
    if (n < N && k < K) out[(size_t)n * K + k] = __float2bfloat16(tile[x][y + i]);
  }
}

// ---------------------------------------------------------------------------
// Embedding
// ---------------------------------------------------------------------------
__global__ void embed_k(const int* __restrict__ x_t, const float* __restrict__ tok,
                        const float* __restrict__ pos, float* __restrict__ h) {
  int row = blockIdx.x;
  int t   = x_t[row];
  int l   = row % Ll;
  const float* te = tok + (size_t)t * Dd;
  const float* pe = pos + (size_t)l * Dd;
  float* ho = h + (size_t)row * Dd;
  for (int d = threadIdx.x; d < Dd; d += blockDim.x) ho[d] = te[d] + pe[d];
}

// ---------------------------------------------------------------------------
// Sigma conditioning MLP
// ---------------------------------------------------------------------------
__global__ void sigma_cond_k(const float* __restrict__ sigma,
                             const float* __restrict__ w1, const float* __restrict__ b1,
                             const float* __restrict__ w2, const float* __restrict__ b2,
                             float* __restrict__ c) {
  __shared__ float emb[FREQ];
  __shared__ float hid[CND];
  int b = blockIdx.x, i = threadIdx.x;
  float sg  = sigma[b];
  float f   = expf(-logf(10000.f) * (float)i / (float)(FREQ / 2));
  float arg = sg * f;
  emb[i]            = cosf(arg);
  emb[i + FREQ / 2] = sinf(arg);
  __syncthreads();
  float acc = b1[i];
  for (int j = 0; j < FREQ; j++) acc += emb[j] * w1[j * CND + i];
  hid[i] = siluf(acc);
  __syncthreads();
  float acc2 = b2[i];
  for (int j = 0; j < CND; j++) acc2 += hid[j] * w2[j * CND + i];
  c[b * CND + i] = acc2;
}

__global__ void adaln_cond_k(const float* __restrict__ c, const float* __restrict__ W,
                             const float* __restrict__ bias, float* __restrict__ cond) {
  int o = blockIdx.x * blockDim.x + threadIdx.x;
  if (o >= Bb * 3 * Dd) return;
  int b = o / (3 * Dd), col = o % (3 * Dd);
  float acc = bias[col];
  const float* cb = c + b * CND;
  for (int j = 0; j < CND; j++) acc += cb[j] * W[(size_t)j * 3 * Dd + col];
  cond[o] = acc;
}

// ---------------------------------------------------------------------------
// LayerNorm + adaLN modulate -> bf16 output
// ---------------------------------------------------------------------------
__global__ void ln_mod_k(const float* __restrict__ h, const float* __restrict__ cond,
                         __nv_bfloat16* __restrict__ out) {
  __shared__ float red[256];
  int row = blockIdx.x, tid = threadIdx.x;
  int b = row / Ll;
  const float* x = h + (size_t)row * Dd;
  float v0 = x[tid], v1 = x[tid + 256], v2 = x[tid + 512];
  red[tid] = v0 + v1 + v2;
  __syncthreads();
  for (int s = 128; s > 0; s >>= 1) { if (tid < s) red[tid] += red[tid + s]; __syncthreads(); }
  float mu = red[0] / (float)Dd;
  __syncthreads();
  float d0 = v0 - mu, d1 = v1 - mu, d2 = v2 - mu;
  red[tid] = d0 * d0 + d1 * d1 + d2 * d2;
  __syncthreads();
  for (int s = 128; s > 0; s >>= 1) { if (tid < s) red[tid] += red[tid + s]; __syncthreads(); }
  float r = rsqrtf(red[0] / (float)Dd + 1e-5f);
  const float* shift = cond + (size_t)b * 3 * Dd;
  const float* scale = shift + Dd;
  __nv_bfloat16* o = out + (size_t)row * Dd;
  o[tid]       = __float2bfloat16(d0 * r * (1.f + scale[tid])       + shift[tid]);
  o[tid + 256] = __float2bfloat16(d1 * r * (1.f + scale[tid + 256]) + shift[tid + 256]);
  o[tid + 512] = __float2bfloat16(d2 * r * (1.f + scale[tid + 512]) + shift[tid + 512]);
}

// ---------------------------------------------------------------------------
// Tensor-core bf16 GEMM: C[M,N](fp32, +opt bf16) = A[M,K](bf16) @ Bt[N,K]^T
// 128x128 block tile, BK=32, 8 warps (2x4), m16n8k16 HMMA.
// ---------------------------------------------------------------------------
__device__ __forceinline__ void mma16816(float* c, const unsigned* a, const unsigned* b) {
  asm volatile(
      "mma.sync.aligned.m16n8k16.row.col.f32.bf16.bf16.f32 "
      "{%0,%1,%2,%3}, {%4,%5,%6,%7}, {%8,%9}, {%0,%1,%2,%3};\n"
      : "+f"(c[0]), "+f"(c[1]), "+f"(c[2]), "+f"(c[3])
      : "r"(a[0]), "r"(a[1]), "r"(a[2]), "r"(a[3]), "r"(b[0]), "r"(b[1]));
}

template <bool GATHER>
__global__ void gemm_bf16_k(const __nv_bfloat16* __restrict__ A, int lda,
                            const __nv_bfloat16* __restrict__ Bt, int ldb,
                            float* __restrict__ C, int ldc,
                            __nv_bfloat16* __restrict__ Cb,
                            int M, int Nn, int K,
                            const int* __restrict__ midx,
                            const int* __restrict__ mcount) {
  constexpr int SA = 40;   // padded row stride (halves); conflict-free for frag loads
  __shared__ __nv_bfloat16 As[128 * SA];
  __shared__ __nv_bfloat16 Bs[128 * SA];
  __shared__ int rowsm[128];
  int tid = threadIdx.x;
  int m0 = blockIdx.y * 128, n0 = blockIdx.x * 128;
  if (GATHER) {
    M = *mcount;
    if (m0 >= M) return;
    if (tid < 128) rowsm[tid] = (m0 + tid < M) ? midx[m0 + tid] : -1;
    __syncthreads();
  }
  int warp = tid >> 5, lane = tid & 31;
  int wm = warp & 1, wn = warp >> 1;       // 2 x 4 warp grid
  int gr = lane >> 2, tc = lane & 3;
  float acc[4][4][4] = {};

  for (int k0 = 0; k0 < K; k0 += 32) {
#pragma unroll
    for (int t = 0; t < 2; t++) {
      int idx = tid + t * 256;
      int r = idx >> 2, cu = (idx & 3) * 8;
      int gk = k0 + cu;
      uint4 v = make_uint4(0u, 0u, 0u, 0u);
      int gm = GATHER ? rowsm[r] : (m0 + r);
      if (gk < K && (!GATHER || gm >= 0))
        v = *reinterpret_cast<const uint4*>(A + (size_t)gm * lda + gk);
      *reinterpret_cast<uint4*>(&As[r * SA + cu]) = v;
    }
#pragma unroll
    for (int t = 0; t < 2; t++) {
      int idx = tid + t * 256;
      int r = idx >> 2, cu = (idx & 3) * 8;
      int gk = k0 + cu;
      int gn = n0 + r;
      uint4 v = make_uint4(0u, 0u, 0u, 0u);
      if (gk < K && gn < Nn)
        v = *reinterpret_cast<const uint4*>(Bt + (size_t)gn * ldb + gk);
      *reinterpret_cast<uint4*>(&Bs[r * SA + cu]) = v;
    }
    __syncthreads();
#pragma unroll
    for (int ks = 0; ks < 2; ks++) {
      int kk = ks * 16;
      unsigned ra[4][4], rb[4][2];
#pragma unroll
      for (int mi = 0; mi < 4; mi++) {
        const __nv_bfloat16* p = &As[(wm * 64 + mi * 16 + gr) * SA + kk + tc * 2];
        ra[mi][0] = *reinterpret_cast<const unsigned*>(p);
        ra[mi][1] = *reinterpret_cast<const unsigned*>(p + 8 * SA);
        ra[mi][2] = *reinterpret_cast<const unsigned*>(p + 8);
        ra[mi][3] = *reinterpret_cast<const unsigned*>(p + 8 * SA + 8);
      }
#pragma unroll
      for (int ni = 0; ni < 4; ni++) {
        const __nv_bfloat16* p = &Bs[(wn * 32 + ni * 8 + gr) * SA + kk + tc * 2];
        rb[ni][0] = *reinterpret_cast<const unsigned*>(p);
        rb[ni][1] = *reinterpret_cast<const unsigned*>(p + 8);
      }
#pragma unroll
      for (int mi = 0; mi < 4; mi++)
#pragma unroll
        for (int ni = 0; ni < 4; ni++)
          mma16816(acc[mi][ni], ra[mi], rb[ni]);
    }
    __syncthreads();
  }

#pragma unroll
  for (int mi = 0; mi < 4; mi++) {
    int lr = wm * 64 + mi * 16 + gr;
    int gm0, gm1;
    if (GATHER) { gm0 = rowsm[lr]; gm1 = rowsm[lr + 8]; }
    else        { gm0 = m0 + lr;   gm1 = gm0 + 8; }
#pragma unroll
    for (int ni = 0; ni < 4; ni++) {
      int col = n0 + wn * 32 + ni * 8 + tc * 2;
      if (col >= Nn) continue;
      const float* c = acc[mi][ni];
      if (!GATHER || gm0 >= 0) {
        *reinterpret_cast<float2*>(C + (size_t)gm0 * ldc + col) = make_float2(c[0], c[1]);
        if (Cb)
          *reinterpret_cast<__nv_bfloat162*>(Cb + (size_t)gm0 * ldc + col) =
              __floats2bfloat162_rn(c[0], c[1]);
      }
      if (!GATHER || gm1 >= 0) {
        *reinterpret_cast<float2*>(C + (size_t)gm1 * ldc + col) = make_float2(c[2], c[3]);
        if (Cb)
          *reinterpret_cast<__nv_bfloat162*>(Cb + (size_t)gm1 * ldc + col) =
              __floats2bfloat162_rn(c[2], c[3]);
      }
    }
  }
}

// ---------------------------------------------------------------------------
// delta = softplus(delta + dt_bias[d])
// ---------------------------------------------------------------------------
__global__ void softplus_bias_k(float* __restrict__ delta, const float* __restrict__ dtb) {
  int i = blockIdx.x * blockDim.x + threadIdx.x;
  if (i >= BL * DI) return;
  float x = delta[i] + dtb[i % DI];
  delta[i] = fmaxf(x, 0.f) + log1pf(__expf(-fabsf(x)));
}

// ---------------------------------------------------------------------------
// Selective scan (fp32)
// ---------------------------------------------------------------------------
__global__ void scan_k(const float* __restrict__ delta, const float* __restrict__ xz,
                       const float* __restrict__ dtbc, const float* __restrict__ A_log,
                       float* __restrict__ y, int backward) {
  int tid = threadIdx.x;
  int nloc = tid & 15, dloc = tid >> 4;
  int d = blockIdx.x * 16 + dloc;
  int b = blockIdx.y;
  float a = -expf(A_log[d * Ns + nloc]);
  float hst = 0.f;
  for (int s = 0; s < Ll; s++) {
    int t = backward ? (Ll - 1 - s) : s;
    size_t row = (size_t)b * Ll + t;
    float dl = delta[row * DI + d];
    float u  = xz[row * 2 * DI + d];
    float Bv = dtbc[row * DTBC + DTR + nloc];
    float Cv = dtbc[row * DTBC + DTR + Ns + nloc];
    hst = __expf(dl * a) * hst + dl * u * Bv;
    float ctr = hst * Cv;
    ctr += __shfl_down_sync(0xffffffffu, ctr, 8, 16);
    ctr += __shfl_down_sync(0xffffffffu, ctr, 4, 16);
    ctr += __shfl_down_sync(0xffffffffu, ctr, 2, 16);
    ctr += __shfl_down_sync(0xffffffffu, ctr, 1, 16);
    if (nloc == 0) y[row * DI + d] = ctr;
  }
}

// ---------------------------------------------------------------------------
// out_bf16 = (y + u*Dskip) * silu(z)
// ---------------------------------------------------------------------------
__global__ void gate_k(const float* __restrict__ y, const float* __restrict__ xz,
                       const float* __restrict__ Dsk, __nv_bfloat16* __restrict__ out) {
  int i = blockIdx.x * blockDim.x + threadIdx.x;
  if (i >= BL * DI) return;
  int d = i % DI;
  size_t row = (size_t)(i / DI);
  float u = xz[row * 2 * DI + d];
  float z = xz[row * 2 * DI + DI + d];
  out[i] = __float2bfloat16((y[i] + u * Dsk[d]) * siluf(z));
}

__global__ void combine_k(float* __restrict__ h, const float* __restrict__ cond,
                          const float* __restrict__ p0, const float* __restrict__ p1) {
  int i = blockIdx.x * blockDim.x + threadIdx.x;
  if (i >= BL * Dd) return;
  int d = i % Dd;
  int b = i / (Ll * Dd);
  float g = cond[(size_t)b * 3 * Dd + 2 * Dd + d];
  float v = p0[i];
  if (p1) v += p1[i];
  h[i] += g * v;
}

__global__ void silu_mul_k(const float* __restrict__ a, const float* __restrict__ bm,
                           __nv_bfloat16* __restrict__ out) {
  int i = blockIdx.x * blockDim.x + threadIdx.x;
  if (i >= BL * Hh) return;
  out[i] = __float2bfloat16(siluf(a[i]) * bm[i]);
}

// ---------------------------------------------------------------------------
// Masked-row compaction
// ---------------------------------------------------------------------------
__global__ void build_mask_k(const int* __restrict__ x_t, int* __restrict__ midx,
                             int* __restrict__ mcount) {
  __shared__ int sf[BL];
  int i = threadIdx.x;
  int f = (x_t[i] == MASKID) ? 1 : 0;
  sf[i] = f;
  __syncthreads();
  for (int off = 1; off < BL; off <<= 1) {
    int v = (i >= off) ? sf[i - off] : 0;
    __syncthreads();
    sf[i] += v;
    __syncthreads();
  }
  if (f) midx[sf[i] - 1] = i;
  if (i == BL - 1) *mcount = sf[i];
}

__global__ void fill_forced_k(const int* __restrict__ x_t, float* __restrict__ out) {
  int row = blockIdx.x;
  int tok = x_t[row];
  if (tok == MASKID) return;
  float4* o = reinterpret_cast<float4*>(out + (size_t)row * Vv);
  for (int v4 = threadIdx.x; v4 < Vv / 4; v4 += blockDim.x) {
    int v = v4 * 4;
    float4 val = make_float4(NEGF, NEGF, NEGF, NEGF);
    if (tok >= v && tok < v + 4) (&val.x)[tok - v] = 0.f;
    o[v4] = val;
  }
}

__global__ void log_softmax_k(const int* __restrict__ x_t, float* __restrict__ out) {
  __shared__ float red[256];
  int row = blockIdx.x;
  if (x_t[row] != MASKID) return;
  float* o = out + (size_t)row * Vv;
  int tid = threadIdx.x;
  float m = NEGF;
  for (int v = tid; v < Vv; v += 256)
    if (v != MASKID) m = fmaxf(m, o[v]);
  red[tid] = m;
  __syncthreads();
  for (int s = 128; s > 0; s >>= 1) { if (tid < s) red[tid] = fmaxf(red[tid], red[tid + s]); __syncthreads(); }
  m = red[0];
  __syncthreads();
  float sum = 0.f;
  for (int v = tid; v < Vv; v += 256)
    if (v != MASKID) sum += __expf(o[v] - m);
  red[tid] = sum;
  __syncthreads();
  for (int s = 128; s > 0; s >>= 1) { if (tid < s) red[tid] += red[tid + s]; __syncthreads(); }
  float lse = m + logf(red[0]);
  __syncthreads();
  for (int v = tid; v < Vv; v += 256)
    o[v] = (v == MASKID) ? NEGF : (o[v] - lse);
}

// ---------------------------------------------------------------------------
// Host
// ---------------------------------------------------------------------------
static inline void run_gemm(const __nv_bfloat16* A, int lda, const __nv_bfloat16* Bt, int ldb,
                            float* C, int ldc, __nv_bfloat16* Cb, int M, int N, int K) {
  dim3 g((N + 127) / 128, (M + 127) / 128);
  gemm_bf16_k<false><<<g, 256>>>(A, lda, Bt, ldb, C, ldc, Cb, M, N, K, nullptr, nullptr);
}

static inline void run_tconv(const float* in, __nv_bfloat16* out, int K, int N) {
  dim3 g((N + 31) / 32, (K + 31) / 32);
  tconv_k<<<g, dim3(32, 8)>>>(in, out, K, N);
}

extern "C" void kernel_launch(void* const* d_in, const int* in_sizes, int n_in,
                              void* d_out, int out_size) {
  (void)in_sizes; (void)n_in; (void)out_size;
  const int*   x_t      = (const int*)  d_in[0];
  const float* sigma    = (const float*)d_in[1];
  const float* tok_emb  = (const float*)d_in[2];
  const float* pos_emb  = (const float*)d_in[3];
  const float* te_w1    = (const float*)d_in[4];
  const float* te_b1    = (const float*)d_in[5];
  const float* te_w2    = (const float*)d_in[6];
  const float* te_b2    = (const float*)d_in[7];
  const float* adaln1_w = (const float*)d_in[8];
  const float* adaln1_b = (const float*)d_in[9];
  const float* adaln2_w = (const float*)d_in[10];
  const float* adaln2_b = (const float*)d_in[11];
  const float* Win      = (const float*)d_in[12];
  const float* Wx       = (const float*)d_in[13];
  const float* Wdt      = (const float*)d_in[14];
  const float* dt_bias  = (const float*)d_in[15];
  const float* A_log    = (const float*)d_in[16];
  const float* Dskip    = (const float*)d_in[17];
  const float* Wout     = (const float*)d_in[18];
  const float* mlp_w1   = (const float*)d_in[19];
  const float* mlp_w2   = (const float*)d_in[20];
  const float* mlp_w3   = (const float*)d_in[21];
  const float* oad_w    = (const float*)d_in[22];
  const float* oad_b    = (const float*)d_in[23];
  float* out = (float*)d_out;

  float* buf = nullptr;
  __nv_bfloat16* bfp = nullptr;
  int* midx = nullptr;
  int* mcount = nullptr;
  cudaGetSymbolAddress((void**)&buf, g_buf);
  cudaGetSymbolAddress((void**)&bfp, g_bf);
  cudaGetSymbolAddress((void**)&midx, g_midx);
  cudaGetSymbolAddress((void**)&mcount, g_mcount);

  float* h     = buf + OFF_H;
  float* c     = buf + OFF_C;
  float* cond  = buf + OFF_COND;
  float* xz[2]    = {buf + OFF_XZ,    buf + OFF_XZ    + S_XZ};
  float* dtbc[2]  = {buf + OFF_DTBC,  buf + OFF_DTBC  + S_DTBC};
  float* delta[2] = {buf + OFF_DELTA, buf + OFF_DELTA + S_DEL};
  float* yb[2]    = {buf + OFF_Y,     buf + OFF_Y     + S_DEL};
  float* yo[2]    = {buf + OFF_YO,    buf + OFF_YO    + S_YO};
  float* mlpa  = buf + OFF_MLPA;
  float* mlpb  = buf + OFF_MLPB;

  __nv_bfloat16* TE    = bfp + HB_TE;
  __nv_bfloat16* normb = bfp + HB_NORM;
  __nv_bfloat16* xzb[2]   = {bfp + HB_XZ,   bfp + HB_XZ   + (size_t)BL * 2 * DI};
  __nv_bfloat16* dtbcb[2] = {bfp + HB_DTBC, bfp + HB_DTBC + (size_t)BL * DTBC};
  __nv_bfloat16* ybb[2]   = {bfp + HB_Y,    bfp + HB_Y    + (size_t)BL * DI};
  __nv_bfloat16* mlpab = bfp + HB_MLPA;

  // ---- weight preprocessing (bf16 + transpose to [N][K]) ----
  {
    int n = Vv * Dd;
    conv_k<<<(n / 4 + 255) / 256, 256>>>(tok_emb, TE, n);
  }
  for (int li = 0; li < 4; li++) {
    run_tconv(Win  + (size_t)li * Dd * 2 * DI, bfp + HB_WINT  + (size_t)li * HS_WINT,  Dd, 2 * DI);
    run_tconv(Wx   + (size_t)li * DI * DTBC,   bfp + HB_WXT   + (size_t)li * HS_WXT,   DI, DTBC);
    run_tconv(Wdt  + (size_t)li * DTR * DI,    bfp + HB_WDTT  + (size_t)li * HS_WDTT,  DTR, DI);
    run_tconv(Wout + (size_t)li * DI * Dd,     bfp + HB_WOUTT + (size_t)li * HS_WOUTT, DI, Dd);
  }
  for (int l = 0; l < NL; l++) {
    run_tconv(mlp_w1 + (size_t)l * Dd * Hh, bfp + HB_W12T + (size_t)(2 * l)     * HS_W12T, Dd, Hh);
    run_tconv(mlp_w2 + (size_t)l * Dd * Hh, bfp + HB_W12T + (size_t)(2 * l + 1) * HS_W12T, Dd, Hh);
    run_tconv(mlp_w3 + (size_t)l * Hh * Dd, bfp + HB_W3T  + (size_t)l * HS_W3T, Hh, Dd);
  }

  embed_k<<<BL, 256>>>(x_t, tok_emb, pos_emb, h);
  sigma_cond_k<<<Bb, 128>>>(sigma, te_w1, te_b1, te_w2, te_b2, c);
  build_mask_k<<<1, BL>>>(x_t, midx, mcount);
  fill_forced_k<<<BL, 256>>>(x_t, out);

  const int EW_DI = (BL * DI + 255) / 256;
  const int EW_D  = (BL * Dd + 255) / 256;
  const int EW_H  = (BL * Hh + 255) / 256;

  for (int l = 0; l < NL; l++) {
    // ---- SSM block ----
    adaln_cond_k<<<(Bb * 3 * Dd) / 256, 256>>>(c, adaln1_w + (size_t)l * CND * 3 * Dd,
                                               adaln1_b + (size_t)l * 3 * Dd, cond);
    ln_mod_k<<<BL, 256>>>(h, cond, normb);
    for (int dir = 0; dir < 2; dir++) {
      int li = l * 2 + dir;
      run_gemm(normb, Dd, bfp + HB_WINT + (size_t)li * HS_WINT, Dd,
               xz[dir], 2 * DI, xzb[dir], BL, 2 * DI, Dd);
      run_gemm(xzb[dir], 2 * DI, bfp + HB_WXT + (size_t)li * HS_WXT, DI,
               dtbc[dir], DTBC, dtbcb[dir], BL, DTBC, DI);
      run_gemm(dtbcb[dir], DTBC, bfp + HB_WDTT + (size_t)li * HS_WDTT, DTR,
               delta[dir], DI, nullptr, BL, DI, DTR);
      softplus_bias_k<<<EW_DI, 256>>>(delta[dir], dt_bias + (size_t)li * DI);
    }
    for (int dir = 0; dir < 2; dir++) {
      int li = l * 2 + dir;
      scan_k<<<dim3(DI / 16, Bb), 256>>>(delta[dir], xz[dir], dtbc[dir],
                                         A_log + (size_t)li * DI * Ns, yb[dir], dir);
    }
    for (int dir = 0; dir < 2; dir++) {
      int li = l * 2 + dir;
      gate_k<<<EW_DI, 256>>>(yb[dir], xz[dir], Dskip + (size_t)li * DI, ybb[dir]);
      run_gemm(ybb[dir], DI, bfp + HB_WOUTT + (size_t)li * HS_WOUTT, DI,
               yo[dir], Dd, nullptr, BL, Dd, DI);
    }
    combine_k<<<EW_D, 256>>>(h, cond, yo[0], yo[1]);

    // ---- MLP block ----
    adaln_cond_k<<<(Bb * 3 * Dd) / 256, 256>>>(c, adaln2_w + (size_t)l * CND * 3 * Dd,
                                               adaln2_b + (size_t)l * 3 * Dd, cond);
    ln_mod_k<<<BL, 256>>>(h, cond, normb);
    run_gemm(normb, Dd, bfp + HB_W12T + (size_t)(2 * l)     * HS_W12T, Dd,
             mlpa, Hh, nullptr, BL, Hh, Dd);
    run_gemm(normb, Dd, bfp + HB_W12T + (size_t)(2 * l + 1) * HS_W12T, Dd,
             mlpb, Hh, nullptr, BL, Hh, Dd);
    silu_mul_k<<<EW_H, 256>>>(mlpa, mlpb, mlpab);
    run_gemm(mlpab, Hh, bfp + HB_W3T + (size_t)l * HS_W3T, Hh,
             yo[0], Dd, nullptr, BL, Dd, Hh);
    combine_k<<<EW_D, 256>>>(h, cond, yo[0], nullptr);
  }

  // ---- Output head ----
  adaln_cond_k<<<(Bb * 3 * Dd) / 256, 256>>>(c, oad_w, oad_b, cond);
  ln_mod_k<<<BL, 256>>>(h, cond, normb);
  {
    dim3 g(Vv / 128 + (Vv % 128 ? 1 : 0), BL / 128);
    gemm_bf16_k<true><<<g, 256>>>(normb, Dd, TE, Dd, out, Vv, nullptr,
                                  BL, Vv, Dd, midx, mcount);
  }
  log_softmax_k<<<BL, 256>>>(x_t, out);
}

// round 5
// speedup vs baseline: 2.7062x; 1.1242x over previous
#include <cuda_runtime.h>
#include <cuda_bf16.h>
#include <math.h>

// ---------------------------------------------------------------------------
// Problem constants
// ---------------------------------------------------------------------------
namespace {
constexpr int Bb   = 2;
constexpr int Ll   = 512;
constexpr int Vv   = 50304;
constexpr int Dd   = 768;
constexpr int NL   = 2;
constexpr int DI   = 1536;
constexpr int Ns   = 16;
constexpr int DTR  = 48;
constexpr int Hh   = 1536;
constexpr int CND  = 128;
constexpr int FREQ = 256;
constexpr int MASKID = 50257;
constexpr int BL   = Bb * Ll;                 // 1024
constexpr int DTBC = DTR + 2 * Ns;            // 80
constexpr int XZC  = 2 * 2 * DI;              // 6144 combined xz row (2 dirs)

// fp32 scratch pool
constexpr size_t S_H     = (size_t)BL * Dd;
constexpr size_t OFF_H     = 0;
constexpr size_t OFF_C     = OFF_H    + S_H;
constexpr size_t OFF_COND  = OFF_C    + (size_t)Bb * CND;
constexpr size_t OFF_XZC   = OFF_COND + (size_t)Bb * 3 * Dd;
constexpr size_t OFF_DTBC  = OFF_XZC  + (size_t)BL * XZC;
constexpr size_t OFF_DELTA = OFF_DTBC + 2 * (size_t)BL * DTBC;
constexpr size_t OFF_YO    = OFF_DELTA + 2 * (size_t)BL * DI;
constexpr size_t OFF_MLP12 = OFF_YO   + 2 * (size_t)BL * Dd;
constexpr size_t TOTALF    = OFF_MLP12 + (size_t)BL * 2 * Hh;

// bf16 pool
constexpr size_t HS_TE    = (size_t)Vv * Dd;
constexpr size_t HS_WINT  = (size_t)2 * DI * Dd;
constexpr size_t HS_WXT   = (size_t)DTBC * DI;
constexpr size_t HS_WDTT  = (size_t)DI * DTR;
constexpr size_t HS_WOUTT = (size_t)Dd * DI;
constexpr size_t HS_W12T  = (size_t)Hh * Dd;
constexpr size_t HS_W3T   = (size_t)Dd * Hh;

constexpr size_t HB_TE    = 0;
constexpr size_t HB_WINT  = HB_TE    + HS_TE;
constexpr size_t HB_WXT   = HB_WINT  + 4 * HS_WINT;
constexpr size_t HB_WDTT  = HB_WXT   + 4 * HS_WXT;
constexpr size_t HB_WOUTT = HB_WDTT  + 4 * HS_WDTT;
constexpr size_t HB_W12T  = HB_WOUTT + 4 * HS_WOUTT;   // l0w1,l0w2,l1w1,l1w2
constexpr size_t HB_W3T   = HB_W12T  + 4 * HS_W12T;
constexpr size_t HB_NORM  = HB_W3T   + 2 * HS_W3T;
constexpr size_t HB_XZC   = HB_NORM  + (size_t)BL * Dd;
constexpr size_t HB_DTBC  = HB_XZC   + (size_t)BL * XZC;
constexpr size_t HB_Y     = HB_DTBC  + 2 * (size_t)BL * DTBC;
constexpr size_t HB_MLPAB = HB_Y     + 2 * (size_t)BL * DI;
constexpr size_t TOTALH   = HB_MLPAB + (size_t)BL * Hh + 64;

constexpr float NEGF = -3.402823466e38f;
} // namespace

__device__ float g_buf[TOTALF];
__device__ __align__(16) __nv_bfloat16 g_bf[TOTALH];
__device__ int   g_midx[BL];
__device__ int   g_mcount;

__device__ __forceinline__ float siluf(float x) { return x / (1.f + __expf(-x)); }

// ---------------------------------------------------------------------------
// cp.async helper (16B, zero-fill when sz==0)
// ---------------------------------------------------------------------------
__device__ __forceinline__ void cp16(void* smem_dst, const void* gsrc, int szbytes) {
  unsigned s = (unsigned)__cvta_generic_to_shared(smem_dst);
  asm volatile("cp.async.cg.shared.global [%0], [%1], 16, %2;\n"
               :: "r"(s), "l"(gsrc), "r"(szbytes));
}

// ---------------------------------------------------------------------------
// Weight preprocessing
// ---------------------------------------------------------------------------
__global__ void conv_k(const float* __restrict__ in, __nv_bfloat16* __restrict__ out, int n) {
  int i = (blockIdx.x * blockDim.x + threadIdx.x) * 4;
  if (i + 3 >= n) {
    for (; i < n; i++) out[i] = __float2bfloat16(in[i]);
    return;
  }
  float4 v = *reinterpret_cast<const float4*>(in + i);
  *reinterpret_cast<__nv_bfloat162*>(out + i)     = __floats2bfloat162_rn(v.x, v.y);
  *reinterpret_cast<__nv_bfloat162*>(out + i + 2) = __floats2bfloat162_rn(v.z, v.w);
}

// out[n][k] = bf16(in[k][n])
__global__ void tconv_k(const float* __restrict__ in, __nv_bfloat16* __restrict__ out,
                        int K, int N) {
  __shared__ float tile[32][33];
  int k0 = blockIdx.y * 32, n0 = blockIdx.x * 32;
  int x = threadIdx.x, y = threadIdx.y;
#pragma unroll
  for (int i = 0; i < 32; i += 8) {
    int k = k0 + y + i, n = n0 + x;
    tile[y + i][x] = (k < K && n < N) ? in[(size_t)k * N + n] : 0.f;
  }
  __syncthreads();
#pragma unroll
  for (int i = 0; i < 32; i += 8) {
    int n = n0 + y + i, k = k0 + x;
    if (n < N && k < K) out[(size_t)n * K + k] = __float2bfloat16(tile[x][y + i]);
  }
}

// ---------------------------------------------------------------------------
// Small kernels
// ---------------------------------------------------------------------------
__global__ void embed_k(const int* __restrict__ x_t, const float* __restrict__ tok,
                        const float* __restrict__ pos, float* __restrict__ h) {
  int row = blockIdx.x;
  int t   = x_t[row];
  int l   = row % Ll;
  const float* te = tok + (size_t)t * Dd;
  const float* pe = pos + (size_t)l * Dd;
  float* ho = h + (size_t)row * Dd;
  for (int d = threadIdx.x; d < Dd; d += blockDim.x) ho[d] = te[d] + pe[d];
}

__global__ void sigma_cond_k(const float* __restrict__ sigma,
                             const float* __restrict__ w1, const float* __restrict__ b1,
                             const float* __restrict__ w2, const float* __restrict__ b2,
                             float* __restrict__ c) {
  __shared__ float emb[FREQ];
  __shared__ float hid[CND];
  int b = blockIdx.x, i = threadIdx.x;
  float sg  = sigma[b];
  float f   = expf(-logf(10000.f) * (float)i / (float)(FREQ / 2));
  float arg = sg * f;
  emb[i]            = cosf(arg);
  emb[i + FREQ / 2] = sinf(arg);
  __syncthreads();
  float acc = b1[i];
  for (int j = 0; j < FREQ; j++) acc += emb[j] * w1[j * CND + i];
  hid[i] = siluf(acc);
  __syncthreads();
  float acc2 = b2[i];
  for (int j = 0; j < CND; j++) acc2 += hid[j] * w2[j * CND + i];
  c[b * CND + i] = acc2;
}

__global__ void adaln_cond_k(const float* __restrict__ c, const float* __restrict__ W,
                             const float* __restrict__ bias, float* __restrict__ cond) {
  int o = blockIdx.x * blockDim.x + threadIdx.x;
  if (o >= Bb * 3 * Dd) return;
  int b = o / (3 * Dd), col = o % (3 * Dd);
  float acc = bias[col];
  const float* cb = c + b * CND;
  for (int j = 0; j < CND; j++) acc += cb[j] * W[(size_t)j * 3 * Dd + col];
  cond[o] = acc;
}

__global__ void ln_mod_k(const float* __restrict__ h, const float* __restrict__ cond,
                         __nv_bfloat16* __restrict__ out) {
  __shared__ float red[256];
  int row = blockIdx.x, tid = threadIdx.x;
  int b = row / Ll;
  const float* x = h + (size_t)row * Dd;
  float v0 = x[tid], v1 = x[tid + 256], v2 = x[tid + 512];
  red[tid] = v0 + v1 + v2;
  __syncthreads();
  for (int s = 128; s > 0; s >>= 1) { if (tid < s) red[tid] += red[tid + s]; __syncthreads(); }
  float mu = red[0] / (float)Dd;
  __syncthreads();
  float d0 = v0 - mu, d1 = v1 - mu, d2 = v2 - mu;
  red[tid] = d0 * d0 + d1 * d1 + d2 * d2;
  __syncthreads();
  for (int s = 128; s > 0; s >>= 1) { if (tid < s) red[tid] += red[tid + s]; __syncthreads(); }
  float r = rsqrtf(red[0] / (float)Dd + 1e-5f);
  const float* shift = cond + (size_t)b * 3 * Dd;
  const float* scale = shift + Dd;
  __nv_bfloat16* o = out + (size_t)row * Dd;
  o[tid]       = __float2bfloat16(d0 * r * (1.f + scale[tid])       + shift[tid]);
  o[tid + 256] = __float2bfloat16(d1 * r * (1.f + scale[tid + 256]) + shift[tid + 256]);
  o[tid + 512] = __float2bfloat16(d2 * r * (1.f + scale[tid + 512]) + shift[tid + 512]);
}

// ---------------------------------------------------------------------------
// Pipelined bf16 tensor-core GEMM, batched over blockIdx.z.
// C[M,N] = A[M,K] @ Bt[N,K]^T.  128x128x32 tiles, 2-stage cp.async pipeline.
// ---------------------------------------------------------------------------
__device__ __forceinline__ void mma16816(float* c, const unsigned* a, const unsigned* b) {
  asm volatile(
      "mma.sync.aligned.m16n8k16.row.col.f32.bf16.bf16.f32 "
      "{%0,%1,%2,%3}, {%4,%5,%6,%7}, {%8,%9}, {%0,%1,%2,%3};\n"
      : "+f"(c[0]), "+f"(c[1]), "+f"(c[2]), "+f"(c[3])
      : "r"(a[0]), "r"(a[1]), "r"(a[2]), "r"(a[3]), "r"(b[0]), "r"(b[1]));
}

template <bool GATHER>
__global__ void __launch_bounds__(256, 2)
gemm_bf16_k(const __nv_bfloat16* __restrict__ A, int lda, long sA_,
            const __nv_bfloat16* __restrict__ Bt, int ldb, long sB_,
            float* __restrict__ C, int ldc, long sC_,
            __nv_bfloat16* __restrict__ Cb,
            int M, int Nn, int K,
            const int* __restrict__ midx, const int* __restrict__ mcount) {
  constexpr int SA = 40;
  __shared__ __nv_bfloat16 As[2][128 * SA];
  __shared__ __nv_bfloat16 Bs[2][128 * SA];
  __shared__ int rowsm[128];
  int z = blockIdx.z;
  A  += (size_t)z * sA_;
  Bt += (size_t)z * sB_;
  if (C)  C  += (size_t)z * sC_;
  if (Cb) Cb += (size_t)z * sC_;

  int tid = threadIdx.x;
  int m0 = blockIdx.y * 128, n0 = blockIdx.x * 128;
  if (GATHER) {
    M = *mcount;
    if (m0 >= M) return;
    if (tid < 128) rowsm[tid] = (m0 + tid < M) ? midx[m0 + tid] : -1;
    __syncthreads();
  }
  int warp = tid >> 5, lane = tid & 31;
  int wm = warp & 1, wn = warp >> 1;
  int gr = lane >> 2, tc = lane & 3;
  float acc[4][4][4] = {};

  int iters = (K + 31) / 32;

  auto load_stage = [&](int it, int s) {
    int k0 = it * 32;
#pragma unroll
    for (int t = 0; t < 2; t++) {
      int idx = tid + t * 256;
      int r = idx >> 2, cu = (idx & 3) * 8;
      int gk = k0 + cu;
      int gm = GATHER ? rowsm[r] : (m0 + r);
      int ok = (gk < K && gm >= 0) ? 16 : 0;
      if (gm < 0) gm = 0;
      cp16(&As[s][r * SA + cu], A + (size_t)gm * lda + gk, ok);
    }
#pragma unroll
    for (int t = 0; t < 2; t++) {
      int idx = tid + t * 256;
      int r = idx >> 2, cu = (idx & 3) * 8;
      int gk = k0 + cu;
      int gn = n0 + r;
      int ok = (gk < K && gn < Nn) ? 16 : 0;
      if (gn >= Nn) gn = 0;
      cp16(&Bs[s][r * SA + cu], Bt + (size_t)gn * ldb + gk, ok);
    }
  };

  load_stage(0, 0);
  asm volatile("cp.async.commit_group;\n");

  for (int it = 0; it < iters; it++) {
    if (it + 1 < iters) {
      load_stage(it + 1, (it + 1) & 1);
      asm volatile("cp.async.commit_group;\n");
      asm volatile("cp.async.wait_group 1;\n");
    } else {
      asm volatile("cp.async.wait_group 0;\n");
    }
    __syncthreads();
    int s = it & 1;
#pragma unroll
    for (int ks = 0; ks < 2; ks++) {
      int kk = ks * 16;
      unsigned ra[4][4], rb[4][2];
#pragma unroll
      for (int mi = 0; mi < 4; mi++) {
        const __nv_bfloat16* p = &As[s][(wm * 64 + mi * 16 + gr) * SA + kk + tc * 2];
        ra[mi][0] = *reinterpret_cast<const unsigned*>(p);
        ra[mi][1] = *reinterpret_cast<const unsigned*>(p + 8 * SA);
        ra[mi][2] = *reinterpret_cast<const unsigned*>(p + 8);
        ra[mi][3] = *reinterpret_cast<const unsigned*>(p + 8 * SA + 8);
      }
#pragma unroll
      for (int ni = 0; ni < 4; ni++) {
        const __nv_bfloat16* p = &Bs[s][(wn * 32 + ni * 8 + gr) * SA + kk + tc * 2];
        rb[ni][0] = *reinterpret_cast<const unsigned*>(p);
        rb[ni][1] = *reinterpret_cast<const unsigned*>(p + 8);
      }
#pragma unroll
      for (int mi = 0; mi < 4; mi++)
#pragma unroll
        for (int ni = 0; ni < 4; ni++)
          mma16816(acc[mi][ni], ra[mi], rb[ni]);
    }
    __syncthreads();
  }

#pragma unroll
  for (int mi = 0; mi < 4; mi++) {
    int lr = wm * 64 + mi * 16 + gr;
    int gm0, gm1;
    if (GATHER) { gm0 = rowsm[lr]; gm1 = rowsm[lr + 8]; }
    else        { gm0 = m0 + lr;   gm1 = gm0 + 8; }
#pragma unroll
    for (int ni = 0; ni < 4; ni++) {
      int col = n0 + wn * 32 + ni * 8 + tc * 2;
      if (col >= Nn) continue;
      const float* cc = acc[mi][ni];
      if (gm0 >= 0) {
        if (C)  *reinterpret_cast<float2*>(C + (size_t)gm0 * ldc + col) = make_float2(cc[0], cc[1]);
        if (Cb) *reinterpret_cast<__nv_bfloat162*>(Cb + (size_t)gm0 * ldc + col) =
                    __floats2bfloat162_rn(cc[0], cc[1]);
      }
      if (gm1 >= 0) {
        if (C)  *reinterpret_cast<float2*>(C + (size_t)gm1 * ldc + col) = make_float2(cc[2], cc[3]);
        if (Cb) *reinterpret_cast<__nv_bfloat162*>(Cb + (size_t)gm1 * ldc + col) =
                    __floats2bfloat162_rn(cc[2], cc[3]);
      }
    }
  }
}

// ---------------------------------------------------------------------------
// Fused selective scan: softplus(delta+bias), scan, gate, bf16 out.
// grid = (DI/16, B, 2 dirs), block = 256 (16 d x 16 n)
// ---------------------------------------------------------------------------
__global__ void scan_k(const float* __restrict__ delta_raw,  // [2][BL][DI]
                       const float* __restrict__ xzc,        // [BL][XZC]
                       const float* __restrict__ dtbc,       // [2][BL][DTBC]
                       const float* __restrict__ A_log,      // [2][DI][Ns]
                       const float* __restrict__ dt_bias,    // [2][DI]
                       const float* __restrict__ Dsk,        // [2][DI]
                       __nv_bfloat16* __restrict__ yb) {     // [2][BL][DI]
  int tid = threadIdx.x;
  int nloc = tid & 15, dloc = tid >> 4;
  int d = blockIdx.x * 16 + dloc;
  int b = blockIdx.y;
  int dir = blockIdx.z;
  float a    = -expf(A_log[((size_t)dir * DI + d) * Ns + nloc]);
  float bias = dt_bias[dir * DI + d];
  float dskv = Dsk[dir * DI + d];
  const float* delp = delta_raw + (size_t)dir * BL * DI;
  const float* dtp  = dtbc + (size_t)dir * BL * DTBC;
  __nv_bfloat16* yp = yb + (size_t)dir * BL * DI;
  float hst = 0.f;
  for (int s = 0; s < Ll; s++) {
    int t = dir ? (Ll - 1 - s) : s;
    size_t row = (size_t)b * Ll + t;
    float dlr = delp[row * DI + d] + bias;
    float dl  = fmaxf(dlr, 0.f) + __logf(1.f + __expf(-fabsf(dlr)));
    float u   = xzc[row * XZC + dir * 2 * DI + d];
    float Bv  = dtp[row * DTBC + DTR + nloc];
    float Cv  = dtp[row * DTBC + DTR + Ns + nloc];
    hst = fmaf(__expf(dl * a), hst, dl * u * Bv);
    float ctr = hst * Cv;
    ctr += __shfl_down_sync(0xffffffffu, ctr, 8, 16);
    ctr += __shfl_down_sync(0xffffffffu, ctr, 4, 16);
    ctr += __shfl_down_sync(0xffffffffu, ctr, 2, 16);
    ctr += __shfl_down_sync(0xffffffffu, ctr, 1, 16);
    if (nloc == 0) {
      float zz = xzc[row * XZC + dir * 2 * DI + DI + d];
      yp[row * DI + d] = __float2bfloat16((ctr + u * dskv) * siluf(zz));
    }
  }
}

__global__ void combine_k(float* __restrict__ h, const float* __restrict__ cond,
                          const float* __restrict__ p0, const float* __restrict__ p1) {
  int i = blockIdx.x * blockDim.x + threadIdx.x;
  if (i >= BL * Dd) return;
  int d = i % Dd;
  int b = i / (Ll * Dd);
  float g = cond[(size_t)b * 3 * Dd + 2 * Dd + d];
  float v = p0[i];
  if (p1) v += p1[i];
  h[i] += g * v;
}

// mlpab[row][hc] = silu(mlp12[row][hc]) * mlp12[row][Hh+hc]
__global__ void silu_mul_k(const float* __restrict__ m12, __nv_bfloat16* __restrict__ out) {
  int i = blockIdx.x * blockDim.x + threadIdx.x;
  if (i >= BL * Hh) return;
  int row = i / Hh, hc = i % Hh;
  float av = m12[(size_t)row * 2 * Hh + hc];
  float bv = m12[(size_t)row * 2 * Hh + Hh + hc];
  out[i] = __float2bfloat16(siluf(av) * bv);
}

__global__ void build_mask_k(const int* __restrict__ x_t, int* __restrict__ midx,
                             int* __restrict__ mcount) {
  __shared__ int sf[BL];
  int i = threadIdx.x;
  int f = (x_t[i] == MASKID) ? 1 : 0;
  sf[i] = f;
  __syncthreads();
  for (int off = 1; off < BL; off <<= 1) {
    int v = (i >= off) ? sf[i - off] : 0;
    __syncthreads();
    sf[i] += v;
    __syncthreads();
  }
  if (f) midx[sf[i] - 1] = i;
  if (i == BL - 1) *mcount = sf[i];
}

__global__ void fill_forced_k(const int* __restrict__ x_t, float* __restrict__ out) {
  int row = blockIdx.x;
  int tok = x_t[row];
  if (tok == MASKID) return;
  float4* o = reinterpret_cast<float4*>(out + (size_t)row * Vv);
  for (int v4 = threadIdx.x; v4 < Vv / 4; v4 += blockDim.x) {
    int v = v4 * 4;
    float4 val = make_float4(NEGF, NEGF, NEGF, NEGF);
    if (tok >= v && tok < v + 4) (&val.x)[tok - v] = 0.f;
    o[v4] = val;
  }
}

__global__ void log_softmax_k(const int* __restrict__ x_t, float* __restrict__ out) {
  __shared__ float red[256];
  int row = blockIdx.x;
  if (x_t[row] != MASKID) return;
  float* o = out + (size_t)row * Vv;
  int tid = threadIdx.x;
  float m = NEGF;
  for (int v = tid; v < Vv; v += 256)
    if (v != MASKID) m = fmaxf(m, o[v]);
  red[tid] = m;
  __syncthreads();
  for (int s = 128; s > 0; s >>= 1) { if (tid < s) red[tid] = fmaxf(red[tid], red[tid + s]); __syncthreads(); }
  m = red[0];
  __syncthreads();
  float sum = 0.f;
  for (int v = tid; v < Vv; v += 256)
    if (v != MASKID) sum += __expf(o[v] - m);
  red[tid] = sum;
  __syncthreads();
  for (int s = 128; s > 0; s >>= 1) { if (tid < s) red[tid] += red[tid + s]; __syncthreads(); }
  float lse = m + logf(red[0]);
  __syncthreads();
  for (int v = tid; v < Vv; v += 256)
    o[v] = (v == MASKID) ? NEGF : (o[v] - lse);
}

// ---------------------------------------------------------------------------
// Host
// ---------------------------------------------------------------------------
static inline void run_gemm(const __nv_bfloat16* A, int lda, long sA,
                            const __nv_bfloat16* Bt, int ldb, long sB,
                            float* C, int ldc, long sC, __nv_bfloat16* Cb,
                            int M, int N, int K, int nz) {
  dim3 g((N + 127) / 128, (M + 127) / 128, nz);
  gemm_bf16_k<false><<<g, 256>>>(A, lda, sA, Bt, ldb, sB, C, ldc, sC, Cb,
                                 M, N, K, nullptr, nullptr);
}

static inline void run_tconv(const float* in, __nv_bfloat16* out, int K, int N) {
  dim3 g((N + 31) / 32, (K + 31) / 32);
  tconv_k<<<g, dim3(32, 8)>>>(in, out, K, N);
}

extern "C" void kernel_launch(void* const* d_in, const int* in_sizes, int n_in,
                              void* d_out, int out_size) {
  (void)in_sizes; (void)n_in; (void)out_size;
  const int*   x_t      = (const int*)  d_in[0];
  const float* sigma    = (const float*)d_in[1];
  const float* tok_emb  = (const float*)d_in[2];
  const float* pos_emb  = (const float*)d_in[3];
  const float* te_w1    = (const float*)d_in[4];
  const float* te_b1    = (const float*)d_in[5];
  const float* te_w2    = (const float*)d_in[6];
  const float* te_b2    = (const float*)d_in[7];
  const float* adaln1_w = (const float*)d_in[8];
  const float* adaln1_b = (const float*)d_in[9];
  const float* adaln2_w = (const float*)d_in[10];
  const float* adaln2_b = (const float*)d_in[11];
  const float* Win      = (const float*)d_in[12];
  const float* Wx       = (const float*)d_in[13];
  const float* Wdt      = (const float*)d_in[14];
  const float* dt_bias  = (const float*)d_in[15];
  const float* A_log    = (const float*)d_in[16];
  const float* Dskip    = (const float*)d_in[17];
  const float* Wout     = (const float*)d_in[18];
  const float* mlp_w1   = (const float*)d_in[19];
  const float* mlp_w2   = (const float*)d_in[20];
  const float* mlp_w3   = (const float*)d_in[21];
  const float* oad_w    = (const float*)d_in[22];
  const float* oad_b    = (const float*)d_in[23];
  float* out = (float*)d_out;

  float* buf = nullptr;
  __nv_bfloat16* bfp = nullptr;
  int* midx = nullptr;
  int* mcount = nullptr;
  cudaGetSymbolAddress((void**)&buf, g_buf);
  cudaGetSymbolAddress((void**)&bfp, g_bf);
  cudaGetSymbolAddress((void**)&midx, g_midx);
  cudaGetSymbolAddress((void**)&mcount, g_mcount);

  float* h     = buf + OFF_H;
  float* c     = buf + OFF_C;
  float* cond  = buf + OFF_COND;
  float* xzc   = buf + OFF_XZC;
  float* dtbc  = buf + OFF_DTBC;
  float* delta = buf + OFF_DELTA;
  float* yo    = buf + OFF_YO;
  float* mlp12 = buf + OFF_MLP12;

  __nv_bfloat16* TE    = bfp + HB_TE;
  __nv_bfloat16* normb = bfp + HB_NORM;
  __nv_bfloat16* xzcb  = bfp + HB_XZC;
  __nv_bfloat16* dtbcb = bfp + HB_DTBC;
  __nv_bfloat16* ybb   = bfp + HB_Y;
  __nv_bfloat16* mlpab = bfp + HB_MLPAB;

  // ---- weight preprocessing ----
  {
    int n = Vv * Dd;
    conv_k<<<(n / 4 + 255) / 256, 256>>>(tok_emb, TE, n);
  }
  for (int li = 0; li < 4; li++) {
    run_tconv(Win  + (size_t)li * Dd * 2 * DI, bfp + HB_WINT  + (size_t)li * HS_WINT,  Dd, 2 * DI);
    run_tconv(Wx   + (size_t)li * DI * DTBC,   bfp + HB_WXT   + (size_t)li * HS_WXT,   DI, DTBC);
    run_tconv(Wdt  + (size_t)li * DTR * DI,    bfp + HB_WDTT  + (size_t)li * HS_WDTT,  DTR, DI);
    run_tconv(Wout + (size_t)li * DI * Dd,     bfp + HB_WOUTT + (size_t)li * HS_WOUTT, DI, Dd);
  }
  for (int l = 0; l < NL; l++) {
    run_tconv(mlp_w1 + (size_t)l * Dd * Hh, bfp + HB_W12T + (size_t)(2 * l)     * HS_W12T, Dd, Hh);
    run_tconv(mlp_w2 + (size_t)l * Dd * Hh, bfp + HB_W12T + (size_t)(2 * l + 1) * HS_W12T, Dd, Hh);
    run_tconv(mlp_w3 + (size_t)l * Hh * Dd, bfp + HB_W3T  + (size_t)l * HS_W3T, Hh, Dd);
  }

  embed_k<<<BL, 256>>>(x_t, tok_emb, pos_emb, h);
  sigma_cond_k<<<Bb, 128>>>(sigma, te_w1, te_b1, te_w2, te_b2, c);
  build_mask_k<<<1, BL>>>(x_t, midx, mcount);
  fill_forced_k<<<BL, 256>>>(x_t, out);

  const int EW_D  = (BL * Dd + 255) / 256;
  const int EW_H  = (BL * Hh + 255) / 256;

  for (int l = 0; l < NL; l++) {
    // ---- SSM block ----
    adaln_cond_k<<<(Bb * 3 * Dd) / 256, 256>>>(c, adaln1_w + (size_t)l * CND * 3 * Dd,
                                               adaln1_b + (size_t)l * 3 * Dd, cond);
    ln_mod_k<<<BL, 256>>>(h, cond, normb);
    // Win both dirs as one GEMM: N = 6144
    run_gemm(normb, Dd, 0, bfp + HB_WINT + (size_t)(2 * l) * HS_WINT, Dd, 0,
             xzc, XZC, 0, xzcb, BL, XZC, Dd, 1);
    // Wx batched over dir: A = u half of xzc, N = 80, K = 1536
    run_gemm(xzcb, XZC, (long)(2 * DI), bfp + HB_WXT + (size_t)(2 * l) * HS_WXT, DI, (long)HS_WXT,
             dtbc, DTBC, (long)BL * DTBC, dtbcb, BL, DTBC, DI, 2);
    // Wdt batched: N = 1536, K = 48
    run_gemm(dtbcb, DTBC, (long)BL * DTBC, bfp + HB_WDTT + (size_t)(2 * l) * HS_WDTT, DTR, (long)HS_WDTT,
             delta, DI, (long)BL * DI, nullptr, BL, DI, DTR, 2);
    // fused scan (softplus + scan + gate), both dirs
    scan_k<<<dim3(DI / 16, Bb, 2), 256>>>(delta, xzc, dtbc,
                                          A_log + (size_t)l * 2 * DI * Ns,
                                          dt_bias + (size_t)l * 2 * DI,
                                          Dskip + (size_t)l * 2 * DI, ybb);
    // Wout batched: N = 768, K = 1536
    run_gemm(ybb, DI, (long)BL * DI, bfp + HB_WOUTT + (size_t)(2 * l) * HS_WOUTT, DI, (long)HS_WOUTT,
             yo, Dd, (long)BL * Dd, nullptr, BL, Dd, DI, 2);
    combine_k<<<EW_D, 256>>>(h, cond, yo, yo + (size_t)BL * Dd);

    // ---- MLP block ----
    adaln_cond_k<<<(Bb * 3 * Dd) / 256, 256>>>(c, adaln2_w + (size_t)l * CND * 3 * Dd,
                                               adaln2_b + (size_t)l * 3 * Dd, cond);
    ln_mod_k<<<BL, 256>>>(h, cond, normb);
    // w1+w2 as one GEMM: N = 3072
    run_gemm(normb, Dd, 0, bfp + HB_W12T + (size_t)(2 * l) * HS_W12T, Dd, 0,
             mlp12, 2 * Hh, 0, nullptr, BL, 2 * Hh, Dd, 1);
    silu_mul_k<<<EW_H, 256>>>(mlp12, mlpab);
    run_gemm(mlpab, Hh, 0, bfp + HB_W3T + (size_t)l * HS_W3T, Hh, 0,
             yo, Dd, 0, nullptr, BL, Dd, Hh, 1);
    combine_k<<<EW_D, 256>>>(h, cond, yo, nullptr);
  }

  // ---- Output head ----
  adaln_cond_k<<<(Bb * 3 * Dd) / 256, 256>>>(c, oad_w, oad_b, cond);
  ln_mod_k<<<BL, 256>>>(h, cond, normb);
  {
    dim3 g((Vv + 127) / 128, BL / 128, 1);
    gemm_bf16_k<true><<<g, 256>>>(normb, Dd, 0, TE, Dd, 0, out, Vv, 0, nullptr,
                                  BL, Vv, Dd, midx, mcount);
  }
  log_softmax_k<<<BL, 256>>>(x_t, out);
}

// round 6
// speedup vs baseline: 2.8570x; 1.0557x over previous
#include <cuda_runtime.h>
#include <cuda_bf16.h>
#include <math.h>

// ---------------------------------------------------------------------------
// Problem constants
// ---------------------------------------------------------------------------
namespace {
constexpr int Bb   = 2;
constexpr int Ll   = 512;
constexpr int Vv   = 50304;
constexpr int Dd   = 768;
constexpr int NL   = 2;
constexpr int DI   = 1536;
constexpr int Ns   = 16;
constexpr int DTR  = 48;
constexpr int Hh   = 1536;
constexpr int CND  = 128;
constexpr int FREQ = 256;
constexpr int MASKID = 50257;
constexpr int BL   = Bb * Ll;                 // 1024
constexpr int DTBC = DTR + 2 * Ns;            // 80
constexpr int XZC  = 2 * 2 * DI;              // 6144 combined xz row (2 dirs)

// fp32 scratch pool
constexpr size_t S_H     = (size_t)BL * Dd;
constexpr size_t OFF_H     = 0;
constexpr size_t OFF_C     = OFF_H    + S_H;
constexpr size_t OFF_COND  = OFF_C    + (size_t)Bb * CND;
constexpr size_t OFF_XZC   = OFF_COND + (size_t)Bb * 3 * Dd;
constexpr size_t OFF_DTBC  = OFF_XZC  + (size_t)BL * XZC;
constexpr size_t OFF_DELTA = OFF_DTBC + 2 * (size_t)BL * DTBC;
constexpr size_t OFF_YO    = OFF_DELTA + 2 * (size_t)BL * DI;
constexpr size_t OFF_MLP12 = OFF_YO   + 2 * (size_t)BL * Dd;
constexpr size_t TOTALF    = OFF_MLP12 + (size_t)BL * 2 * Hh;

// bf16 pool
constexpr size_t HS_TE    = (size_t)Vv * Dd;
constexpr size_t HS_WINT  = (size_t)2 * DI * Dd;
constexpr size_t HS_WXT   = (size_t)DTBC * DI;
constexpr size_t HS_WDTT  = (size_t)DI * DTR;
constexpr size_t HS_WOUTT = (size_t)Dd * DI;
constexpr size_t HS_W12T  = (size_t)Hh * Dd;
constexpr size_t HS_W3T   = (size_t)Dd * Hh;

constexpr size_t HB_TE    = 0;
constexpr size_t HB_WINT  = HB_TE    + HS_TE;
constexpr size_t HB_WXT   = HB_WINT  + 4 * HS_WINT;
constexpr size_t HB_WDTT  = HB_WXT   + 4 * HS_WXT;
constexpr size_t HB_WOUTT = HB_WDTT  + 4 * HS_WDTT;
constexpr size_t HB_W12T  = HB_WOUTT + 4 * HS_WOUTT;   // l0w1,l0w2,l1w1,l1w2
constexpr size_t HB_W3T   = HB_W12T  + 4 * HS_W12T;
constexpr size_t HB_NORM  = HB_W3T   + 2 * HS_W3T;
constexpr size_t HB_XZC   = HB_NORM  + (size_t)BL * Dd;
constexpr size_t HB_DTBC  = HB_XZC   + (size_t)BL * XZC;
constexpr size_t HB_Y     = HB_DTBC  + 2 * (size_t)BL * DTBC;
constexpr size_t HB_MLPAB = HB_Y     + 2 * (size_t)BL * DI;
constexpr size_t TOTALH   = HB_MLPAB + (size_t)BL * Hh + 64;

constexpr float NEGF = -3.402823466e38f;

constexpr int GSTAGES = 3;
constexpr int GSA     = 40;                            // smem row stride (halves)
constexpr int GSMEM   = GSTAGES * 2 * 128 * GSA * 2;   // 61440 bytes dynamic
} // namespace

__device__ float g_buf[TOTALF];
__device__ __align__(16) __nv_bfloat16 g_bf[TOTALH];
__device__ int   g_midx[BL];
__device__ int   g_mcount;

__device__ __forceinline__ float siluf(float x) { return x / (1.f + __expf(-x)); }

__device__ __forceinline__ void cp16(void* smem_dst, const void* gsrc, int szbytes) {
  unsigned s = (unsigned)__cvta_generic_to_shared(smem_dst);
  asm volatile("cp.async.cg.shared.global [%0], [%1], 16, %2;\n"
               :: "r"(s), "l"(gsrc), "r"(szbytes));
}

__device__ __forceinline__ void ldsm4(unsigned& r0, unsigned& r1, unsigned& r2, unsigned& r3,
                                      const void* p) {
  unsigned a = (unsigned)__cvta_generic_to_shared(p);
  asm volatile("ldmatrix.sync.aligned.m8n8.x4.shared.b16 {%0,%1,%2,%3}, [%4];\n"
               : "=r"(r0), "=r"(r1), "=r"(r2), "=r"(r3) : "r"(a));
}

// ---------------------------------------------------------------------------
// Weight preprocessing
// ---------------------------------------------------------------------------
__global__ void conv_k(const float* __restrict__ in, __nv_bfloat16* __restrict__ out, int n) {
  int i = (blockIdx.x * blockDim.x + threadIdx.x) * 4;
  if (i + 3 >= n) {
    for (; i < n; i++) out[i] = __float2bfloat16(in[i]);
    return;
  }
  float4 v = *reinterpret_cast<const float4*>(in + i);
  *reinterpret_cast<__nv_bfloat162*>(out + i)     = __floats2bfloat162_rn(v.x, v.y);
  *reinterpret_cast<__nv_bfloat162*>(out + i + 2) = __floats2bfloat162_rn(v.z, v.w);
}

// out[n][k] = bf16(in[k][n]), batched over blockIdx.z with strides
__global__ void tconv_k(const float* __restrict__ in, __nv_bfloat16* __restrict__ out,
                        int K, int N, long instr, long outstr) {
  __shared__ float tile[32][33];
  in  += (size_t)blockIdx.z * instr;
  out += (size_t)blockIdx.z * outstr;
  int k0 = blockIdx.y * 32, n0 = blockIdx.x * 32;
  int x = threadIdx.x, y = threadIdx.y;
#pragma unroll
  for (int i = 0; i < 32; i += 8) {
    int k = k0 + y + i, n = n0 + x;
    tile[y + i][x] = (k < K && n < N) ? in[(size_t)k * N + n] : 0.f;
  }
  __syncthreads();
#pragma unroll
  for (int i = 0; i < 32; i += 8) {
    int n = n0 + y + i, k = k0 + x;
    if (n < N && k < K) out[(size_t)n * K + k] = __float2bfloat16(tile[x][y + i]);
  }
}

// ---------------------------------------------------------------------------
// Small kernels
// ---------------------------------------------------------------------------
__global__ void embed_k(const int* __restrict__ x_t, const float* __restrict__ tok,
                        const float* __restrict__ pos, float* __restrict__ h) {
  int row = blockIdx.x;
  int t   = x_t[row];
  int l   = row % Ll;
  const float* te = tok + (size_t)t * Dd;
  const float* pe = pos + (size_t)l * Dd;
  float* ho = h + (size_t)row * Dd;
  for (int d = threadIdx.x; d < Dd; d += blockDim.x) ho[d] = te[d] + pe[d];
}

__global__ void sigma_cond_k(const float* __restrict__ sigma,
                             const float* __restrict__ w1, const float* __restrict__ b1,
                             const float* __restrict__ w2, const float* __restrict__ b2,
                             float* __restrict__ c) {
  __shared__ float emb[FREQ];
  __shared__ float hid[CND];
  int b = blockIdx.x, i = threadIdx.x;
  float sg  = sigma[b];
  float f   = expf(-logf(10000.f) * (float)i / (float)(FREQ / 2));
  float arg = sg * f;
  emb[i]            = cosf(arg);
  emb[i + FREQ / 2] = sinf(arg);
  __syncthreads();
  float acc = b1[i];
  for (int j = 0; j < FREQ; j++) acc += emb[j] * w1[j * CND + i];
  hid[i] = siluf(acc);
  __syncthreads();
  float acc2 = b2[i];
  for (int j = 0; j < CND; j++) acc2 += hid[j] * w2[j * CND + i];
  c[b * CND + i] = acc2;
}

__global__ void adaln_cond_k(const float* __restrict__ c, const float* __restrict__ W,
                             const float* __restrict__ bias, float* __restrict__ cond) {
  int o = blockIdx.x * blockDim.x + threadIdx.x;
  if (o >= Bb * 3 * Dd) return;
  int b = o / (3 * Dd), col = o % (3 * Dd);
  float acc = bias[col];
  const float* cb = c + b * CND;
  for (int j = 0; j < CND; j++) acc += cb[j] * W[(size_t)j * 3 * Dd + col];
  cond[o] = acc;
}

__global__ void ln_mod_k(const float* __restrict__ h, const float* __restrict__ cond,
                         __nv_bfloat16* __restrict__ out) {
  __shared__ float red[256];
  int row = blockIdx.x, tid = threadIdx.x;
  int b = row / Ll;
  const float* x = h + (size_t)row * Dd;
  float v0 = x[tid], v1 = x[tid + 256], v2 = x[tid + 512];
  red[tid] = v0 + v1 + v2;
  __syncthreads();
  for (int s = 128; s > 0; s >>= 1) { if (tid < s) red[tid] += red[tid + s]; __syncthreads(); }
  float mu = red[0] / (float)Dd;
  __syncthreads();
  float d0 = v0 - mu, d1 = v1 - mu, d2 = v2 - mu;
  red[tid] = d0 * d0 + d1 * d1 + d2 * d2;
  __syncthreads();
  for (int s = 128; s > 0; s >>= 1) { if (tid < s) red[tid] += red[tid + s]; __syncthreads(); }
  float r = rsqrtf(red[0] / (float)Dd + 1e-5f);
  const float* shift = cond + (size_t)b * 3 * Dd;
  const float* scale = shift + Dd;
  __nv_bfloat16* o = out + (size_t)row * Dd;
  o[tid]       = __float2bfloat16(d0 * r * (1.f + scale[tid])       + shift[tid]);
  o[tid + 256] = __float2bfloat16(d1 * r * (1.f + scale[tid + 256]) + shift[tid + 256]);
  o[tid + 512] = __float2bfloat16(d2 * r * (1.f + scale[tid + 512]) + shift[tid + 512]);
}

// ---------------------------------------------------------------------------
// Pipelined bf16 tensor-core GEMM, 3-stage cp.async, ldmatrix fragments.
// C[M,N] = A[M,K] @ Bt[N,K]^T.  128x128x32 tiles, batched over blockIdx.z.
// ---------------------------------------------------------------------------
__device__ __forceinline__ void mma16816(float* c, const unsigned* a, const unsigned* b) {
  asm volatile(
      "mma.sync.aligned.m16n8k16.row.col.f32.bf16.bf16.f32 "
      "{%0,%1,%2,%3}, {%4,%5,%6,%7}, {%8,%9}, {%0,%1,%2,%3};\n"
      : "+f"(c[0]), "+f"(c[1]), "+f"(c[2]), "+f"(c[3])
      : "r"(a[0]), "r"(a[1]), "r"(a[2]), "r"(a[3]), "r"(b[0]), "r"(b[1]));
}

template <bool GATHER>
__global__ void __launch_bounds__(256, 2)
gemm_bf16_k(const __nv_bfloat16* __restrict__ A, int lda, long sA_,
            const __nv_bfloat16* __restrict__ Bt, int ldb, long sB_,
            float* __restrict__ C, int ldc, long sC_,
            __nv_bfloat16* __restrict__ Cb,
            int M, int Nn, int K,
            const int* __restrict__ midx, const int* __restrict__ mcount) {
  extern __shared__ __nv_bfloat16 smemdyn[];
  __nv_bfloat16* As = smemdyn;                       // [GSTAGES][128*GSA]
  __nv_bfloat16* Bs = smemdyn + GSTAGES * 128 * GSA; // [GSTAGES][128*GSA]
  __shared__ int rowsm[128];

  int z = blockIdx.z;
  A  += (size_t)z * sA_;
  Bt += (size_t)z * sB_;
  if (C)  C  += (size_t)z * sC_;
  if (Cb) Cb += (size_t)z * sC_;

  int tid = threadIdx.x;
  int m0 = blockIdx.y * 128, n0 = blockIdx.x * 128;
  if (GATHER) {
    M = *mcount;
    if (m0 >= M) return;
    if (tid < 128) rowsm[tid] = (m0 + tid < M) ? midx[m0 + tid] : -1;
    __syncthreads();
  }
  int warp = tid >> 5, lane = tid & 31;
  int wm = warp & 1, wn = warp >> 1;
  int gr = lane >> 2, tc = lane & 3;
  float acc[4][4][4] = {};

  // ldmatrix per-lane base offsets (halves)
  int arow = (wm * 64 + (lane & 15)) * GSA + (lane >> 4) * 8;
  int brow = (wn * 32 + (lane >> 4) * 8 + (lane & 7)) * GSA + ((lane >> 3) & 1) * 8;

  int iters = (K + 31) / 32;

  auto load_stage = [&](int it, int s) {
    __nv_bfloat16* as = As + s * 128 * GSA;
    __nv_bfloat16* bs = Bs + s * 128 * GSA;
    int k0 = it * 32;
#pragma unroll
    for (int t = 0; t < 2; t++) {
      int idx = tid + t * 256;
      int r = idx >> 2, cu = (idx & 3) * 8;
      int gk = k0 + cu;
      int gm = GATHER ? rowsm[r] : (m0 + r);
      int ok = (gk < K && gm >= 0) ? 16 : 0;
      if (gm < 0) gm = 0;
      cp16(&as[r * GSA + cu], A + (size_t)gm * lda + gk, ok);
    }
#pragma unroll
    for (int t = 0; t < 2; t++) {
      int idx = tid + t * 256;
      int r = idx >> 2, cu = (idx & 3) * 8;
      int gk = k0 + cu;
      int gn = n0 + r;
      int ok = (gk < K && gn < Nn) ? 16 : 0;
      if (gn >= Nn) gn = 0;
      cp16(&bs[r * GSA + cu], Bt + (size_t)gn * ldb + gk, ok);
    }
  };

  // prologue: fill first two stages
  load_stage(0, 0);
  asm volatile("cp.async.commit_group;\n");
  if (iters > 1) load_stage(1, 1);
  asm volatile("cp.async.commit_group;\n");

  for (int it = 0; it < iters; it++) {
    asm volatile("cp.async.wait_group 1;\n");
    __syncthreads();
    if (it + GSTAGES - 1 < iters) load_stage(it + GSTAGES - 1, (it + GSTAGES - 1) % GSTAGES);
    asm volatile("cp.async.commit_group;\n");

    int s = it % GSTAGES;
    const __nv_bfloat16* as = As + s * 128 * GSA;
    const __nv_bfloat16* bs = Bs + s * 128 * GSA;
#pragma unroll
    for (int ks = 0; ks < 2; ks++) {
      int kk = ks * 16;
      unsigned ra[4][4], rb[4][2];
#pragma unroll
      for (int mi = 0; mi < 4; mi++)
        ldsm4(ra[mi][0], ra[mi][1], ra[mi][2], ra[mi][3], &as[arow + mi * 16 * GSA + kk]);
#pragma unroll
      for (int p = 0; p < 2; p++)
        ldsm4(rb[2 * p][0], rb[2 * p][1], rb[2 * p + 1][0], rb[2 * p + 1][1],
              &bs[brow + p * 16 * GSA + kk]);
#pragma unroll
      for (int mi = 0; mi < 4; mi++)
#pragma unroll
        for (int ni = 0; ni < 4; ni++)
          mma16816(acc[mi][ni], ra[mi], rb[ni]);
    }
    __syncthreads();
  }

#pragma unroll
  for (int mi = 0; mi < 4; mi++) {
    int lr = wm * 64 + mi * 16 + gr;
    int gm0, gm1;
    if (GATHER) { gm0 = rowsm[lr]; gm1 = rowsm[lr + 8]; }
    else        { gm0 = m0 + lr;   gm1 = gm0 + 8; }
#pragma unroll
    for (int ni = 0; ni < 4; ni++) {
      int col = n0 + wn * 32 + ni * 8 + tc * 2;
      if (col >= Nn) continue;
      const float* cc = acc[mi][ni];
      if (gm0 >= 0) {
        if (C)  *reinterpret_cast<float2*>(C + (size_t)gm0 * ldc + col) = make_float2(cc[0], cc[1]);
        if (Cb) *reinterpret_cast<__nv_bfloat162*>(Cb + (size_t)gm0 * ldc + col) =
                    __floats2bfloat162_rn(cc[0], cc[1]);
      }
      if (gm1 >= 0) {
        if (C)  *reinterpret_cast<float2*>(C + (size_t)gm1 * ldc + col) = make_float2(cc[2], cc[3]);
        if (Cb) *reinterpret_cast<__nv_bfloat162*>(Cb + (size_t)gm1 * ldc + col) =
                    __floats2bfloat162_rn(cc[2], cc[3]);
      }
    }
  }
}

// ---------------------------------------------------------------------------
// Fused selective scan: softplus(delta+bias), scan, gate, bf16 out.
// ---------------------------------------------------------------------------
__global__ void scan_k(const float* __restrict__ delta_raw,  // [2][BL][DI]
                       const float* __restrict__ xzc,        // [BL][XZC]
                       const float* __restrict__ dtbc,       // [2][BL][DTBC]
                       const float* __restrict__ A_log,      // [2][DI][Ns]
                       const float* __restrict__ dt_bias,    // [2][DI]
                       const float* __restrict__ Dsk,        // [2][DI]
                       __nv_bfloat16* __restrict__ yb) {     // [2][BL][DI]
  int tid = threadIdx.x;
  int nloc = tid & 15, dloc = tid >> 4;
  int d = blockIdx.x * 16 + dloc;
  int b = blockIdx.y;
  int dir = blockIdx.z;
  float a    = -expf(A_log[((size_t)dir * DI + d) * Ns + nloc]);
  float bias = dt_bias[dir * DI + d];
  float dskv = Dsk[dir * DI + d];
  const float* delp = delta_raw + (size_t)dir * BL * DI;
  const float* dtp  = dtbc + (size_t)dir * BL * DTBC;
  __nv_bfloat16* yp = yb + (size_t)dir * BL * DI;
  float hst = 0.f;
  for (int s = 0; s < Ll; s++) {
    int t = dir ? (Ll - 1 - s) : s;
    size_t row = (size_t)b * Ll + t;
    float dlr = delp[row * DI + d] + bias;
    float dl  = fmaxf(dlr, 0.f) + __logf(1.f + __expf(-fabsf(dlr)));
    float u   = xzc[row * XZC + dir * 2 * DI + d];
    float Bv  = dtp[row * DTBC + DTR + nloc];
    float Cv  = dtp[row * DTBC + DTR + Ns + nloc];
    hst = fmaf(__expf(dl * a), hst, dl * u * Bv);
    float ctr = hst * Cv;
    ctr += __shfl_down_sync(0xffffffffu, ctr, 8, 16);
    ctr += __shfl_down_sync(0xffffffffu, ctr, 4, 16);
    ctr += __shfl_down_sync(0xffffffffu, ctr, 2, 16);
    ctr += __shfl_down_sync(0xffffffffu, ctr, 1, 16);
    if (nloc == 0) {
      float zz = xzc[row * XZC + dir * 2 * DI + DI + d];
      yp[row * DI + d] = __float2bfloat16((ctr + u * dskv) * siluf(zz));
    }
  }
}

__global__ void combine_k(float* __restrict__ h, const float* __restrict__ cond,
                          const float* __restrict__ p0, const float* __restrict__ p1) {
  int i = blockIdx.x * blockDim.x + threadIdx.x;
  if (i >= BL * Dd) return;
  int d = i % Dd;
  int b = i / (Ll * Dd);
  float g = cond[(size_t)b * 3 * Dd + 2 * Dd + d];
  float v = p0[i];
  if (p1) v += p1[i];
  h[i] += g * v;
}

__global__ void silu_mul_k(const float* __restrict__ m12, __nv_bfloat16* __restrict__ out) {
  int i = blockIdx.x * blockDim.x + threadIdx.x;
  if (i >= BL * Hh) return;
  int row = i / Hh, hc = i % Hh;
  float av = m12[(size_t)row * 2 * Hh + hc];
  float bv = m12[(size_t)row * 2 * Hh + Hh + hc];
  out[i] = __float2bfloat16(siluf(av) * bv);
}

__global__ void build_mask_k(const int* __restrict__ x_t, int* __restrict__ midx,
                             int* __restrict__ mcount) {
  __shared__ int sf[BL];
  int i = threadIdx.x;
  int f = (x_t[i] == MASKID) ? 1 : 0;
  sf[i] = f;
  __syncthreads();
  for (int off = 1; off < BL; off <<= 1) {
    int v = (i >= off) ? sf[i - off] : 0;
    __syncthreads();
    sf[i] += v;
    __syncthreads();
  }
  if (f) midx[sf[i] - 1] = i;
  if (i == BL - 1) *mcount = sf[i];
}

__global__ void fill_forced_k(const int* __restrict__ x_t, float* __restrict__ out) {
  int row = blockIdx.x;
  int tok = x_t[row];
  if (tok == MASKID) return;
  float4* o = reinterpret_cast<float4*>(out + (size_t)row * Vv);
  for (int v4 = threadIdx.x; v4 < Vv / 4; v4 += blockDim.x) {
    int v = v4 * 4;
    float4 val = make_float4(NEGF, NEGF, NEGF, NEGF);
    if (tok >= v && tok < v + 4) (&val.x)[tok - v] = 0.f;
    o[v4] = val;
  }
}

__global__ void log_softmax_k(const int* __restrict__ x_t, float* __restrict__ out) {
  __shared__ float red[256];
  int row = blockIdx.x;
  if (x_t[row] != MASKID) return;
  float* o = out + (size_t)row * Vv;
  int tid = threadIdx.x;
  float m = NEGF;
  for (int v = tid; v < Vv; v += 256)
    if (v != MASKID) m = fmaxf(m, o[v]);
  red[tid] = m;
  __syncthreads();
  for (int s = 128; s > 0; s >>= 1) { if (tid < s) red[tid] = fmaxf(red[tid], red[tid + s]); __syncthreads(); }
  m = red[0];
  __syncthreads();
  float sum = 0.f;
  for (int v = tid; v < Vv; v += 256)
    if (v != MASKID) sum += __expf(o[v] - m);
  red[tid] = sum;
  __syncthreads();
  for (int s = 128; s > 0; s >>= 1) { if (tid < s) red[tid] += red[tid + s]; __syncthreads(); }
  float lse = m + logf(red[0]);
  __syncthreads();
  for (int v = tid; v < Vv; v += 256)
    o[v] = (v == MASKID) ? NEGF : (o[v] - lse);
}

// ---------------------------------------------------------------------------
// Host
// ---------------------------------------------------------------------------
static inline void run_gemm(const __nv_bfloat16* A, int lda, long sA,
                            const __nv_bfloat16* Bt, int ldb, long sB,
                            float* C, int ldc, long sC, __nv_bfloat16* Cb,
                            int M, int N, int K, int nz) {
  dim3 g((N + 127) / 128, (M + 127) / 128, nz);
  gemm_bf16_k<false><<<g, 256, GSMEM>>>(A, lda, sA, Bt, ldb, sB, C, ldc, sC, Cb,
                                        M, N, K, nullptr, nullptr);
}

static inline void run_tconv(const float* in, __nv_bfloat16* out, int K, int N,
                             int nz, long instr, long outstr) {
  dim3 g((N + 31) / 32, (K + 31) / 32, nz);
  tconv_k<<<g, dim3(32, 8)>>>(in, out, K, N, instr, outstr);
}

extern "C" void kernel_launch(void* const* d_in, const int* in_sizes, int n_in,
                              void* d_out, int out_size) {
  (void)in_sizes; (void)n_in; (void)out_size;
  const int*   x_t      = (const int*)  d_in[0];
  const float* sigma    = (const float*)d_in[1];
  const float* tok_emb  = (const float*)d_in[2];
  const float* pos_emb  = (const float*)d_in[3];
  const float* te_w1    = (const float*)d_in[4];
  const float* te_b1    = (const float*)d_in[5];
  const float* te_w2    = (const float*)d_in[6];
  const float* te_b2    = (const float*)d_in[7];
  const float* adaln1_w = (const float*)d_in[8];
  const float* adaln1_b = (const float*)d_in[9];
  const float* adaln2_w = (const float*)d_in[10];
  const float* adaln2_b = (const float*)d_in[11];
  const float* Win      = (const float*)d_in[12];
  const float* Wx       = (const float*)d_in[13];
  const float* Wdt      = (const float*)d_in[14];
  const float* dt_bias  = (const float*)d_in[15];
  const float* A_log    = (const float*)d_in[16];
  const float* Dskip    = (const float*)d_in[17];
  const float* Wout     = (const float*)d_in[18];
  const float* mlp_w1   = (const float*)d_in[19];
  const float* mlp_w2   = (const float*)d_in[20];
  const float* mlp_w3   = (const float*)d_in[21];
  const float* oad_w    = (const float*)d_in[22];
  const float* oad_b    = (const float*)d_in[23];
  float* out = (float*)d_out;

  cudaFuncSetAttribute(gemm_bf16_k<false>, cudaFuncAttributeMaxDynamicSharedMemorySize, GSMEM);
  cudaFuncSetAttribute(gemm_bf16_k<true>,  cudaFuncAttributeMaxDynamicSharedMemorySize, GSMEM);

  float* buf = nullptr;
  __nv_bfloat16* bfp = nullptr;
  int* midx = nullptr;
  int* mcount = nullptr;
  cudaGetSymbolAddress((void**)&buf, g_buf);
  cudaGetSymbolAddress((void**)&bfp, g_bf);
  cudaGetSymbolAddress((void**)&midx, g_midx);
  cudaGetSymbolAddress((void**)&mcount, g_mcount);

  float* h     = buf + OFF_H;
  float* c     = buf + OFF_C;
  float* cond  = buf + OFF_COND;
  float* xzc   = buf + OFF_XZC;
  float* dtbc  = buf + OFF_DTBC;
  float* delta = buf + OFF_DELTA;
  float* yo    = buf + OFF_YO;
  float* mlp12 = buf + OFF_MLP12;

  __nv_bfloat16* TE    = bfp + HB_TE;
  __nv_bfloat16* normb = bfp + HB_NORM;
  __nv_bfloat16* xzcb  = bfp + HB_XZC;
  __nv_bfloat16* dtbcb = bfp + HB_DTBC;
  __nv_bfloat16* ybb   = bfp + HB_Y;
  __nv_bfloat16* mlpab = bfp + HB_MLPAB;

  // ---- weight preprocessing (batched) ----
  {
    int n = Vv * Dd;
    conv_k<<<(n / 4 + 255) / 256, 256>>>(tok_emb, TE, n);
  }
  run_tconv(Win,  bfp + HB_WINT,  Dd, 2 * DI, 4, (long)Dd * 2 * DI, (long)HS_WINT);
  run_tconv(Wx,   bfp + HB_WXT,   DI, DTBC,   4, (long)DI * DTBC,   (long)HS_WXT);
  run_tconv(Wdt,  bfp + HB_WDTT,  DTR, DI,    4, (long)DTR * DI,    (long)HS_WDTT);
  run_tconv(Wout, bfp + HB_WOUTT, DI, Dd,     4, (long)DI * Dd,     (long)HS_WOUTT);
  run_tconv(mlp_w1, bfp + HB_W12T,            Dd, Hh, 2, (long)Dd * Hh, 2 * (long)HS_W12T);
  run_tconv(mlp_w2, bfp + HB_W12T + HS_W12T,  Dd, Hh, 2, (long)Dd * Hh, 2 * (long)HS_W12T);
  run_tconv(mlp_w3, bfp + HB_W3T,             Hh, Dd, 2, (long)Hh * Dd, (long)HS_W3T);

  embed_k<<<BL, 256>>>(x_t, tok_emb, pos_emb, h);
  sigma_cond_k<<<Bb, 128>>>(sigma, te_w1, te_b1, te_w2, te_b2, c);
  build_mask_k<<<1, BL>>>(x_t, midx, mcount);
  fill_forced_k<<<BL, 256>>>(x_t, out);

  const int EW_D  = (BL * Dd + 255) / 256;
  const int EW_H  = (BL * Hh + 255) / 256;

  for (int l = 0; l < NL; l++) {
    // ---- SSM block ----
    adaln_cond_k<<<(Bb * 3 * Dd) / 256, 256>>>(c, adaln1_w + (size_t)l * CND * 3 * Dd,
                                               adaln1_b + (size_t)l * 3 * Dd, cond);
    ln_mod_k<<<BL, 256>>>(h, cond, normb);
    run_gemm(normb, Dd, 0, bfp + HB_WINT + (size_t)(2 * l) * HS_WINT, Dd, 0,
             xzc, XZC, 0, xzcb, BL, XZC, Dd, 1);
    run_gemm(xzcb, XZC, (long)(2 * DI), bfp + HB_WXT + (size_t)(2 * l) * HS_WXT, DI, (long)HS_WXT,
             dtbc, DTBC, (long)BL * DTBC, dtbcb, BL, DTBC, DI, 2);
    run_gemm(dtbcb, DTBC, (long)BL * DTBC, bfp + HB_WDTT + (size_t)(2 * l) * HS_WDTT, DTR, (long)HS_WDTT,
             delta, DI, (long)BL * DI, nullptr, BL, DI, DTR, 2);
    scan_k<<<dim3(DI / 16, Bb, 2), 256>>>(delta, xzc, dtbc,
                                          A_log + (size_t)l * 2 * DI * Ns,
                                          dt_bias + (size_t)l * 2 * DI,
                                          Dskip + (size_t)l * 2 * DI, ybb);
    run_gemm(ybb, DI, (long)BL * DI, bfp + HB_WOUTT + (size_t)(2 * l) * HS_WOUTT, DI, (long)HS_WOUTT,
             yo, Dd, (long)BL * Dd, nullptr, BL, Dd, DI, 2);
    combine_k<<<EW_D, 256>>>(h, cond, yo, yo + (size_t)BL * Dd);

    // ---- MLP block ----
    adaln_cond_k<<<(Bb * 3 * Dd) / 256, 256>>>(c, adaln2_w + (size_t)l * CND * 3 * Dd,
                                               adaln2_b + (size_t)l * 3 * Dd, cond);
    ln_mod_k<<<BL, 256>>>(h, cond, normb);
    run_gemm(normb, Dd, 0, bfp + HB_W12T + (size_t)(2 * l) * HS_W12T, Dd, 0,
             mlp12, 2 * Hh, 0, nullptr, BL, 2 * Hh, Dd, 1);
    silu_mul_k<<<EW_H, 256>>>(mlp12, mlpab);
    run_gemm(mlpab, Hh, 0, bfp + HB_W3T + (size_t)l * HS_W3T, Hh, 0,
             yo, Dd, 0, nullptr, BL, Dd, Hh, 1);
    combine_k<<<EW_D, 256>>>(h, cond, yo, nullptr);
  }

  // ---- Output head ----
  adaln_cond_k<<<(Bb * 3 * Dd) / 256, 256>>>(c, oad_w, oad_b, cond);
  ln_mod_k<<<BL, 256>>>(h, cond, normb);
  {
    dim3 g((Vv + 127) / 128, BL / 128, 1);
    gemm_bf16_k<true><<<g, 256, GSMEM>>>(normb, Dd, 0, TE, Dd, 0, out, Vv, 0, nullptr,
                                         BL, Vv, Dd, midx, mcount);
  }
  log_softmax_k<<<BL, 256>>>(x_t, out);
}